// round 13
// baseline (speedup 1.0000x reference)
#include <cuda_runtime.h>
#include <cuda_bf16.h>
#include <math.h>
#include <stdint.h>

// ---------------- problem constants ----------------
#define BATCH 16
#define NSTA  565
#define FEAT  2176          // 128*17
#define FLAT  36160         // 565*64
#define ZDIM  1850          // 1280 + 5 + 565

// ---------------- scratch (no cudaMalloc allowed) ----------------
// packed bf16x2 word arrays (low 16 bits = even index), 16B-aligned for uint4 staging
__device__ __align__(16) uint32_t g_w1h[32 * 3 * 64],   g_w1l[32 * 3 * 64];
__device__ __align__(16) uint32_t g_w2h[64 * 32 * 64],  g_w2l[64 * 32 * 64];
__device__ __align__(16) uint32_t g_w3h[128 * 64 * 64], g_w3l[128 * 64 * 64];
__device__ __align__(16) uint32_t g_x1h[(size_t)BATCH * 32 * NSTA * 224];  // [b][co][n][m]
__device__ __align__(16) uint32_t g_x1l[(size_t)BATCH * 32 * NSTA * 224];
__device__ __align__(16) uint32_t g_x2h[(size_t)BATCH * 64 * 80 * 568];    // [b][co][m][n]
__device__ __align__(16) uint32_t g_x2l[(size_t)BATCH * 64 * 80 * 568];
__device__ float g_x3[(size_t)BATCH * 128 * NSTA * 17];      // conv3 out FLAT fp32
__device__ float g_dinv[NSTA];
__device__ float g_normT[NSTA * NSTA];
__device__ float g_bufA[BATCH * NSTA * 64];
__device__ float g_bufB[BATCH * NSTA * 64];
__device__ float g_fc1p[8 * BATCH * 1280];
__device__ float g_fc1[BATCH * 1280];
__device__ float g_extra[BATCH * NSTA];
__device__ float g_z[BATCH * ZDIM];

// ---------------- bf16 helpers ----------------
__device__ __forceinline__ void split2(float v0, float v1, uint32_t& hw, uint32_t& lw) {
    __nv_bfloat16 h0 = __float2bfloat16(v0);
    __nv_bfloat16 h1 = __float2bfloat16(v1);
    float r0 = v0 - __bfloat162float(h0);
    float r1 = v1 - __bfloat162float(h1);
    __nv_bfloat16 l0 = __float2bfloat16(r0);
    __nv_bfloat16 l1 = __float2bfloat16(r1);
    hw = (uint32_t)__bfloat16_as_ushort(h0) | ((uint32_t)__bfloat16_as_ushort(h1) << 16);
    lw = (uint32_t)__bfloat16_as_ushort(l0) | ((uint32_t)__bfloat16_as_ushort(l1) << 16);
}

// mma.m16n8k16 row.col f32.bf16.bf16.f32
__device__ __forceinline__ void mmabf(float* c, const uint32_t* a, uint32_t b0, uint32_t b1) {
    asm volatile(
        "mma.sync.aligned.m16n8k16.row.col.f32.bf16.bf16.f32 "
        "{%0,%1,%2,%3},{%4,%5,%6,%7},{%8,%9},{%0,%1,%2,%3};"
        : "+f"(c[0]), "+f"(c[1]), "+f"(c[2]), "+f"(c[3])
        : "r"(a[0]), "r"(a[1]), "r"(a[2]), "r"(a[3]), "r"(b0), "r"(b1));
}

// ---------------- weight prep: fp32 [CO][CI][125] -> packed bf16x2 hi/lo [CO][CI][64] ----
__global__ void k_wprep(const float* __restrict__ w, uint32_t* __restrict__ wh,
                        uint32_t* __restrict__ wl, int total) {
    int i = blockIdx.x * 256 + threadIdx.x;
    if (i >= total) return;
    int m = i & 63;
    int rest = i >> 6;  // co*CIN + ci
    const float* wr = w + (long)rest * 125;
    float v0 = (2 * m     < 125) ? wr[2 * m]     : 0.f;
    float v1 = (2 * m + 1 < 125) ? wr[2 * m + 1] : 0.f;
    uint32_t a, b;
    split2(v0, v1, a, b);
    wh[i] = a;
    wl[i] = b;
}

// ---------------- graph norm ----------------
__global__ void k_deg(const float* __restrict__ A, float* __restrict__ dinv) {
    int c = blockIdx.x;
    float s = 0.f;
    for (int r = threadIdx.x; r < NSTA; r += 64) s += A[r * NSTA + c];
    __shared__ float red[64];
    red[threadIdx.x] = s;
    __syncthreads();
    for (int o = 32; o > 0; o >>= 1) {
        if (threadIdx.x < o) red[threadIdx.x] += red[threadIdx.x + o];
        __syncthreads();
    }
    if (threadIdx.x == 0) dinv[c] = rsqrtf(red[0] + 1.0f);
}

__global__ void k_norm(const float* __restrict__ A, const float* __restrict__ dinv,
                       float* __restrict__ normT) {
    int c = blockIdx.x;
    float dc = dinv[c];
    for (int r = threadIdx.x; r < NSTA; r += 256) {
        float a = A[r * NSTA + c] + (r == c ? 1.0f : 0.0f);
        normT[c * NSTA + r] = dinv[r] * a * dc;
    }
}

// ---------------- implicit-GEMM conv on 3xBF16 m16n8k16 (conv1, conv2) ----------------
template <int CIN, int COUT, int NW_IN, int TWP, int IVAL, bool WAVIN,
          int NTILE, int MW, int NWC, int WOUT, bool TROUT>
__global__ void __launch_bounds__(256, 2)
k_convb(const float* __restrict__ inf, const uint32_t* __restrict__ inh,
        const uint32_t* __restrict__ inl, const uint32_t* __restrict__ wgh,
        const uint32_t* __restrict__ wgl, const float* __restrict__ bias,
        uint32_t* __restrict__ oh, uint32_t* __restrict__ ol) {
    constexpr int WM = COUT / MW;   // warp M tile
    constexpr int MF = WM / 16;     // A fragments / warp
    constexpr int WN = NTILE / NWC; // warp N tile
    constexpr int NG = WN / 8;      // B groups / warp
    constexpr int OPM = NTILE / 2;  // output word pitch (non-TROUT)
    extern __shared__ uint32_t smu[];
    uint32_t* s_ih = smu;                    // CIN*TWP
    uint32_t* s_il = s_ih + CIN * TWP;       // CIN*TWP
    uint32_t* s_wh = s_il + CIN * TWP;       // COUT*68
    uint32_t* s_wl = s_wh + COUT * 68;       // COUT*68

    int b = blockIdx.x / NSTA, n = blockIdx.x % NSTA;
    int tid = threadIdx.x, lane = tid & 31, wid = tid >> 5;
    int wm = wid / NWC, wn = wid % NWC;
    int nbase = wn * WN;
    int g = lane >> 2, k3 = lane & 3;

    // stage input words
    if (WAVIN) {
        for (int i = tid; i < CIN * NW_IN; i += 256) {
            int ci = i / NW_IN, m = i % NW_IN;
            int t0 = 2 * m, t1 = 2 * m + 1;
            const float* base = inf + ((long)(b * NSTA + n)) * (IVAL * 3) + ci;
            float v0 = (t0 < IVAL) ? base[t0 * 3] : 0.f;
            float v1 = (t1 < IVAL) ? base[t1 * 3] : 0.f;
            uint32_t hw, lw;
            split2(v0, v1, hw, lw);
            s_ih[ci * TWP + m] = hw;
            s_il[ci * TWP + m] = lw;
        }
    } else {
        constexpr int RV = NW_IN / 4;  // uint4 per row
        const uint4* ih4 = (const uint4*)inh;
        const uint4* il4 = (const uint4*)inl;
#pragma unroll
        for (int i = tid; i < CIN * RV; i += 256) {
            int ci = i / RV, v = i % RV;
            long src = (((long)(b * CIN + ci)) * NSTA + n) * RV + v;
            *reinterpret_cast<uint4*>(s_ih + ci * TWP + 4 * v) = ih4[src];
            *reinterpret_cast<uint4*>(s_il + ci * TWP + 4 * v) = il4[src];
        }
    }

    float acc[MF][NG][4];
#pragma unroll
    for (int mf = 0; mf < MF; mf++)
#pragma unroll
        for (int gg = 0; gg < NG; gg++)
#pragma unroll
            for (int q = 0; q < 4; q++) acc[mf][gg][q] = 0.f;

    const uint4* wh4 = (const uint4*)wgh;
    const uint4* wl4 = (const uint4*)wgl;

    for (int ci = 0; ci < CIN; ci++) {
        __syncthreads();
#pragma unroll
        for (int i = tid; i < COUT * 16; i += 256) {
            int co = i >> 4, v = i & 15;
            long src = ((long)co * CIN + ci) * 16 + v;
            *reinterpret_cast<uint4*>(s_wh + co * 68 + 4 * v) = wh4[src];
            *reinterpret_cast<uint4*>(s_wl + co * 68 + 4 * v) = wl4[src];
        }
        __syncthreads();
        const uint32_t* bh = s_ih + ci * TWP;
        const uint32_t* bl = s_il + ci * TWP;
#pragma unroll
        for (int ks = 0; ks < 8; ks++) {
            uint32_t Ah[MF][4], Al[MF][4];
#pragma unroll
            for (int mf = 0; mf < MF; mf++) {
                int co = wm * WM + mf * 16 + g;
                const uint32_t* p = s_wh + co * 68 + ks * 8 + k3;
                Ah[mf][0] = p[0];
                Ah[mf][1] = p[8 * 68];
                Ah[mf][2] = p[4];
                Ah[mf][3] = p[8 * 68 + 4];
                const uint32_t* q = s_wl + co * 68 + ks * 8 + k3;
                Al[mf][0] = q[0];
                Al[mf][1] = q[8 * 68];
                Al[mf][2] = q[4];
                Al[mf][3] = q[8 * 68 + 4];
            }
#pragma unroll
            for (int gg = 0; gg < NG; gg++) {
                int widx = nbase + gg * 8 + g + ks * 8 + k3;
                uint32_t b0h = bh[widx], b1h = bh[widx + 4];
                uint32_t b0l = bl[widx], b1l = bl[widx + 4];
#pragma unroll
                for (int mf = 0; mf < MF; mf++) {
                    mmabf(acc[mf][gg], Ah[mf], b0h, b1h);
                    mmabf(acc[mf][gg], Al[mf], b0h, b1h);
                    mmabf(acc[mf][gg], Ah[mf], b0l, b1l);
                }
            }
        }
    }

    // epilogue: relu(+bias), split to bf16 hi/lo words
#pragma unroll
    for (int mf = 0; mf < MF; mf++) {
#pragma unroll
        for (int gg = 0; gg < NG; gg++) {
            int wo = nbase + gg * 8 + 2 * k3;  // even
            int m = wo >> 1;
#pragma unroll
            for (int half = 0; half < 2; half++) {
                int co = wm * WM + mf * 16 + g + half * 8;
                float bb = bias[co];
                float v0 = acc[mf][gg][half * 2 + 0] + bb;
                float v1 = acc[mf][gg][half * 2 + 1] + bb;
                v0 = (wo < WOUT) ? fmaxf(v0, 0.f) : 0.f;
                v1 = (wo + 1 < WOUT) ? fmaxf(v1, 0.f) : 0.f;
                uint32_t hw, lw;
                split2(v0, v1, hw, lw);
                long idx = TROUT ? (((long)(b * COUT + co)) * 80 + m) * 568 + n
                                 : (((long)(b * COUT + co)) * NSTA + n) * OPM + m;
                oh[idx] = hw;
                ol[idx] = lw;
            }
        }
    }
}

// ---------------- conv3: per (b, wo, station-tile) GEMM on transposed x2 words ----------
__global__ void __launch_bounds__(256, 2)
k_conv3b(const uint32_t* __restrict__ x2h, const uint32_t* __restrict__ x2l,
         const uint32_t* __restrict__ wgh, const uint32_t* __restrict__ wgl,
         const float* __restrict__ bias, float* __restrict__ out) {
    extern __shared__ uint32_t smu[];
    uint32_t* s_ph = smu;                  // 64 x 72
    uint32_t* s_pl = s_ph + 64 * 72;
    uint32_t* s_wh = s_pl + 64 * 72;       // 128 x 68
    uint32_t* s_wl = s_wh + 128 * 68;
    int cta = blockIdx.x;
    int b = cta / (17 * 9);
    int r = cta % (17 * 9);
    int wo = r / 9, nt = r % 9;
    int n0 = (nt == 8) ? 504 : nt * 64;  // 16B-aligned overlap for last tile
    int tid = threadIdx.x, lane = tid & 31, wid = tid >> 5;
    int wm = wid >> 1, wn = wid & 1;     // 4 M x 2 N warps, warp tile 32x32
    int g = lane >> 2, k3 = lane & 3;

    float acc[2][4][4];
#pragma unroll
    for (int mf = 0; mf < 2; mf++)
#pragma unroll
        for (int gg = 0; gg < 4; gg++)
#pragma unroll
            for (int q = 0; q < 4; q++) acc[mf][gg][q] = 0.f;

    const uint4* wh4 = (const uint4*)wgh;
    const uint4* wl4 = (const uint4*)wgl;
    const uint4* ph4 = (const uint4*)x2h;
    const uint4* pl4 = (const uint4*)x2l;

    for (int ci = 0; ci < 64; ci++) {
        __syncthreads();
#pragma unroll
        for (int i = tid; i < 128 * 16; i += 256) {
            int co = i >> 4, v = i & 15;
            long src = ((long)co * 64 + ci) * 16 + v;
            *reinterpret_cast<uint4*>(s_wh + co * 68 + 4 * v) = wh4[src];
            *reinterpret_cast<uint4*>(s_wl + co * 68 + 4 * v) = wl4[src];
        }
#pragma unroll
        for (int i = tid; i < 64 * 16; i += 256) {
            int m = i >> 4, v = i & 15;
            long src = ((((long)(b * 64 + ci)) * 80 + wo + m) * 568 + n0) / 4 + v;
            *reinterpret_cast<uint4*>(s_ph + m * 72 + 4 * v) = ph4[src];
            *reinterpret_cast<uint4*>(s_pl + m * 72 + 4 * v) = pl4[src];
        }
        __syncthreads();
#pragma unroll
        for (int ks = 0; ks < 8; ks++) {
            uint32_t Ah[2][4], Al[2][4];
#pragma unroll
            for (int mf = 0; mf < 2; mf++) {
                int co = wm * 32 + mf * 16 + g;
                const uint32_t* p = s_wh + co * 68 + ks * 8 + k3;
                Ah[mf][0] = p[0];
                Ah[mf][1] = p[8 * 68];
                Ah[mf][2] = p[4];
                Ah[mf][3] = p[8 * 68 + 4];
                const uint32_t* q = s_wl + co * 68 + ks * 8 + k3;
                Al[mf][0] = q[0];
                Al[mf][1] = q[8 * 68];
                Al[mf][2] = q[4];
                Al[mf][3] = q[8 * 68 + 4];
            }
#pragma unroll
            for (int gg = 0; gg < 4; gg++) {
                int base = (ks * 8 + k3) * 72 + wn * 32 + gg * 8 + g;
                uint32_t b0h = s_ph[base], b1h = s_ph[base + 4 * 72];
                uint32_t b0l = s_pl[base], b1l = s_pl[base + 4 * 72];
#pragma unroll
                for (int mf = 0; mf < 2; mf++) {
                    mmabf(acc[mf][gg], Ah[mf], b0h, b1h);
                    mmabf(acc[mf][gg], Al[mf], b0h, b1h);
                    mmabf(acc[mf][gg], Ah[mf], b0l, b1l);
                }
            }
        }
    }
#pragma unroll
    for (int mf = 0; mf < 2; mf++) {
#pragma unroll
        for (int gg = 0; gg < 4; gg++) {
#pragma unroll
            for (int q = 0; q < 4; q++) {
                int co = wm * 32 + mf * 16 + g + ((q >> 1) << 3);
                int n = n0 + wn * 32 + gg * 8 + 2 * k3 + (q & 1);
                if (n < NSTA) {
                    float v = fmaxf(acc[mf][gg][q] + bias[co], 0.f);
                    out[(((long)(b * 128 + co)) * NSTA + n) * 17 + wo] = v;
                }
            }
        }
    }
}

// ---------------- GCN1 x@W on raw-reshape feature windows ----------------
__global__ void k_xw_feat(const float* __restrict__ x3, const float* __restrict__ wg,
                          float* __restrict__ h) {
    __shared__ float srow[4 * FEAT];
    int b = blockIdx.x / 142, ng = blockIdx.x % 142;
    int n0 = ng * 4;
    int tid = threadIdx.x;
    for (int i = tid; i < 4 * FEAT; i += 256) {
        int j = i / FEAT, k = i % FEAT;
        int n = n0 + j;
        srow[i] = (n < NSTA) ? x3[((long)(b * NSTA + n)) * FEAT + k] : 0.f;
    }
    __syncthreads();
    int j = tid >> 6, o = tid & 63;
    int n = n0 + j;
    if (n >= NSTA) return;
    const float* sr = srow + j * FEAT;
    float acc = 0.f;
    for (int k = 0; k < FEAT; k++) acc += sr[k] * wg[k * 64 + o];
    h[((long)(b * NSTA + n)) * 64 + o] = acc;
}

__global__ void k_xw64(const float* __restrict__ x, const float* __restrict__ w,
                       float* __restrict__ h) {
    __shared__ float srow[64];
    long bs = blockIdx.x;
    int tid = threadIdx.x;
    srow[tid] = x[bs * 64 + tid];
    __syncthreads();
    float acc = 0.f;
    for (int k = 0; k < 64; k++) acc += srow[k] * w[k * 64 + tid];
    h[bs * 64 + tid] = acc;
}

template <int ACT>  // 0 = relu, 1 = tanh
__global__ void k_agg(const float* __restrict__ h, const float* __restrict__ normT,
                      const float* __restrict__ bias, float* __restrict__ out) {
    __shared__ float sn[4 * NSTA];
    int b = blockIdx.x / 142, cg = blockIdx.x % 142;
    int c0 = cg * 4;
    int tid = threadIdx.x;  // 64
    for (int i = tid; i < 4 * NSTA; i += 64) {
        int cc = i / NSTA, rr = i % NSTA;
        int c = c0 + cc;
        sn[i] = (c < NSTA) ? normT[c * NSTA + rr] : 0.f;
    }
    __syncthreads();
    float bv = bias[tid];
    float acc[4] = {bv, bv, bv, bv};
    const float* hb = h + (long)b * NSTA * 64;
    for (int rr = 0; rr < NSTA; rr++) {
        float hv = hb[rr * 64 + tid];
#pragma unroll
        for (int q = 0; q < 4; q++) acc[q] += sn[q * NSTA + rr] * hv;
    }
#pragma unroll
    for (int q = 0; q < 4; q++) {
        int c = c0 + q;
        if (c < NSTA) {
            float v = ACT ? tanhf(acc[q]) : fmaxf(acc[q], 0.f);
            out[((long)b * NSTA + c) * 64 + tid] = v;
        }
    }
}

// ---------------- fc1 ----------------
__global__ void k_fc1_part(const float* __restrict__ x, const float* __restrict__ w,
                           float* __restrict__ part) {
    __shared__ float sx[16 * 512];
    int o = blockIdx.x * 128 + threadIdx.x;
    int k0 = blockIdx.y * 4520, k1 = k0 + 4520;
    float acc[16] = {};
    for (int kc = k0; kc < k1; kc += 512) {
        int len = min(512, k1 - kc);
        __syncthreads();
        for (int i = threadIdx.x; i < 16 * len; i += 128) {
            int bb = i / len, kk = i % len;
            sx[bb * 512 + kk] = x[bb * FLAT + kc + kk];
        }
        __syncthreads();
        for (int kk = 0; kk < len; kk++) {
            float wv = w[(long)(kc + kk) * 1280 + o];
#pragma unroll
            for (int bb = 0; bb < 16; bb++) acc[bb] += sx[bb * 512 + kk] * wv;
        }
    }
    for (int bb = 0; bb < 16; bb++) part[(blockIdx.y * 16 + bb) * 1280 + o] = acc[bb];
}

__global__ void k_fc1_fin(const float* __restrict__ part, const float* __restrict__ bias,
                          float* __restrict__ fc1) {
    int idx = blockIdx.x * blockDim.x + threadIdx.x;
    if (idx < 16 * 1280) {
        int b = idx / 1280, o = idx % 1280;
        float s = bias[o];
        for (int ks = 0; ks < 8; ks++) s += part[(ks * 16 + b) * 1280 + o];
        fc1[idx] = fmaxf(s, 0.f);
    }
}

// ---------------- extra / z / heads ----------------
__global__ void k_extra(const float* __restrict__ mv, const float* __restrict__ w,
                        const float* __restrict__ bias, float* __restrict__ out) {
    __shared__ float sx[NSTA];
    int b = blockIdx.x;
    for (int i = threadIdx.x; i < NSTA; i += blockDim.x) sx[i] = mv[b * NSTA + i];
    __syncthreads();
    int j = threadIdx.x;
    if (j < NSTA) {
        float acc = bias[j];
        for (int i = 0; i < NSTA; i++) acc += sx[i] * w[i * NSTA + j];
        out[b * NSTA + j] = fmaxf(acc, 0.f);
    }
}

__global__ void k_buildz(const float* __restrict__ fc1, const float* __restrict__ meta,
                         const float* __restrict__ extra, float* __restrict__ z) {
    int b = blockIdx.x;
    for (int i = threadIdx.x; i < ZDIM; i += blockDim.x) {
        float v;
        if (i < 1280)      v = fc1[b * 1280 + i];
        else if (i < 1285) v = meta[b * 5 + (i - 1280)];
        else               v = extra[b * NSTA + (i - 1285)];
        z[b * ZDIM + i] = v;
    }
}

__global__ void k_heads(const float* __restrict__ z,
                        const float* w0, const float* b0, const float* w1, const float* b1,
                        const float* w2, const float* b2, const float* w3, const float* b3,
                        const float* w4, const float* b4, float* __restrict__ out) {
    extern __shared__ float sz[];  // 16 * 1850
    const float* ws[5] = {w0, w1, w2, w3, w4};
    const float* bs[5] = {b0, b1, b2, b3, b4};
    int h = blockIdx.y;
    const float* w = ws[h];
    const float* bias = bs[h];
    int tid = threadIdx.x;
    for (int i = tid; i < 16 * ZDIM; i += 128) sz[i] = z[i];
    __syncthreads();
    int j = blockIdx.x * 128 + tid;
    if (j >= NSTA) return;
    float acc[16] = {};
    for (int k = 0; k < ZDIM; k++) {
        float wv = w[k * NSTA + j];
#pragma unroll
        for (int b = 0; b < 16; b++) acc[b] += sz[b * ZDIM + k] * wv;
    }
    float bb = bias[j];
    for (int b = 0; b < 16; b++) out[(h * 16 + b) * NSTA + j] = acc[b] + bb;
}

// ---------------- launch ----------------
#define CONV1_K k_convb<3, 32, 512, 516, 1000, true, 448, 2, 4, 438, false>
#define CONV2_K k_convb<32, 64, 224, 228, 0, false, 160, 2, 4, 157, true>

extern "C" void kernel_launch(void* const* d_in, const int* in_sizes, int n_in,
                              void* d_out, int out_size) {
    const float* wav  = (const float*)d_in[0];
    const float* A    = (const float*)d_in[2];
    const float* meta = (const float*)d_in[3];
    const float* mv   = (const float*)d_in[4];
    const float* w1 = (const float*)d_in[5];  const float* b1 = (const float*)d_in[6];
    const float* w2 = (const float*)d_in[7];  const float* b2 = (const float*)d_in[8];
    const float* w3 = (const float*)d_in[9];  const float* b3 = (const float*)d_in[10];
    const float* wg1 = (const float*)d_in[11]; const float* bg1 = (const float*)d_in[12];
    const float* wg2 = (const float*)d_in[13]; const float* bg2 = (const float*)d_in[14];
    const float* wfe = (const float*)d_in[15]; const float* bfe = (const float*)d_in[16];
    const float* wf1 = (const float*)d_in[17]; const float* bf1 = (const float*)d_in[18];
    const float* wpga = (const float*)d_in[19]; const float* bpga = (const float*)d_in[20];
    const float* wpgv = (const float*)d_in[21]; const float* bpgv = (const float*)d_in[22];
    const float* ws03 = (const float*)d_in[23]; const float* bs03 = (const float*)d_in[24];
    const float* ws10 = (const float*)d_in[25]; const float* bs10 = (const float*)d_in[26];
    const float* ws30 = (const float*)d_in[27]; const float* bs30 = (const float*)d_in[28];
    float* out = (float*)d_out;

    uint32_t *pw1h, *pw1l, *pw2h, *pw2l, *pw3h, *pw3l;
    uint32_t *px1h, *px1l, *px2h, *px2l;
    float *px3, *pdinv, *pnorm, *pA, *pB, *ppart, *pfc1, *pextra, *pz;
    cudaGetSymbolAddress((void**)&pw1h, g_w1h);
    cudaGetSymbolAddress((void**)&pw1l, g_w1l);
    cudaGetSymbolAddress((void**)&pw2h, g_w2h);
    cudaGetSymbolAddress((void**)&pw2l, g_w2l);
    cudaGetSymbolAddress((void**)&pw3h, g_w3h);
    cudaGetSymbolAddress((void**)&pw3l, g_w3l);
    cudaGetSymbolAddress((void**)&px1h, g_x1h);
    cudaGetSymbolAddress((void**)&px1l, g_x1l);
    cudaGetSymbolAddress((void**)&px2h, g_x2h);
    cudaGetSymbolAddress((void**)&px2l, g_x2l);
    cudaGetSymbolAddress((void**)&px3, g_x3);
    cudaGetSymbolAddress((void**)&pdinv, g_dinv);
    cudaGetSymbolAddress((void**)&pnorm, g_normT);
    cudaGetSymbolAddress((void**)&pA, g_bufA);
    cudaGetSymbolAddress((void**)&pB, g_bufB);
    cudaGetSymbolAddress((void**)&ppart, g_fc1p);
    cudaGetSymbolAddress((void**)&pfc1, g_fc1);
    cudaGetSymbolAddress((void**)&pextra, g_extra);
    cudaGetSymbolAddress((void**)&pz, g_z);

    const int SM1 = (2 * 3 * 516 + 2 * 32 * 68) * 4;    // 29,792
    const int SM2 = (2 * 32 * 228 + 2 * 64 * 68) * 4;   // 93,184
    const int SM3 = (2 * 64 * 72 + 2 * 128 * 68) * 4;   // 106,496
    const int SMH = 16 * ZDIM * 4;                      // 118,400
    cudaFuncSetAttribute(CONV1_K, cudaFuncAttributeMaxDynamicSharedMemorySize, SM1);
    cudaFuncSetAttribute(CONV2_K, cudaFuncAttributeMaxDynamicSharedMemorySize, SM2);
    cudaFuncSetAttribute(k_conv3b, cudaFuncAttributeMaxDynamicSharedMemorySize, SM3);
    cudaFuncSetAttribute(k_heads, cudaFuncAttributeMaxDynamicSharedMemorySize, SMH);

    // weight prep (packed bf16x2 hi/lo)
    k_wprep<<<(32 * 3 * 64 + 255) / 256, 256>>>(w1, pw1h, pw1l, 32 * 3 * 64);
    k_wprep<<<(64 * 32 * 64 + 255) / 256, 256>>>(w2, pw2h, pw2l, 64 * 32 * 64);
    k_wprep<<<(128 * 64 * 64 + 255) / 256, 256>>>(w3, pw3h, pw3l, 128 * 64 * 64);

    k_deg<<<NSTA, 64>>>(A, pdinv);
    k_norm<<<NSTA, 256>>>(A, pdinv, pnorm);

    CONV1_K<<<BATCH * NSTA, 256, SM1>>>(wav, nullptr, nullptr, pw1h, pw1l, b1, px1h, px1l);
    CONV2_K<<<BATCH * NSTA, 256, SM2>>>(nullptr, px1h, px1l, pw2h, pw2l, b2, px2h, px2l);
    k_conv3b<<<BATCH * 17 * 9, 256, SM3>>>(px2h, px2l, pw3h, pw3l, b3, px3);

    k_xw_feat<<<BATCH * 142, 256>>>(px3, wg1, pA);
    k_agg<0><<<BATCH * 142, 64>>>(pA, pnorm, bg1, pB);
    k_xw64<<<BATCH * NSTA, 64>>>(pB, wg2, pA);
    k_agg<1><<<BATCH * 142, 64>>>(pA, pnorm, bg2, pB);

    k_fc1_part<<<dim3(10, 8), 128>>>(pB, wf1, ppart);
    k_fc1_fin<<<80, 256>>>(ppart, bf1, pfc1);
    k_extra<<<BATCH, 576>>>(mv, wfe, bfe, pextra);
    k_buildz<<<BATCH, 256>>>(pfc1, meta, pextra, pz);

    k_heads<<<dim3(5, 5), 128, SMH>>>(pz, wpga, bpga, wpgv, bpgv, ws03, bs03,
                                      ws10, bs10, ws30, bs30, out);
}

// round 14
// speedup vs baseline: 1.0444x; 1.0444x over previous
#include <cuda_runtime.h>
#include <cuda_bf16.h>
#include <math.h>
#include <stdint.h>

// ---------------- problem constants ----------------
#define BATCH 16
#define NSTA  565
#define FEAT  2176          // 128*17
#define FLAT  36160         // 565*64
#define ZDIM  1850          // 1280 + 5 + 565

// ---------------- scratch (no cudaMalloc allowed) ----------------
__device__ __align__(16) uint32_t g_w1h[32 * 3 * 64],   g_w1l[32 * 3 * 64];
__device__ __align__(16) uint32_t g_w2h[64 * 32 * 64],  g_w2l[64 * 32 * 64];
__device__ __align__(16) uint32_t g_w3h[128 * 64 * 64], g_w3l[128 * 64 * 64];
__device__ __align__(16) uint32_t g_x1h[(size_t)BATCH * 32 * NSTA * 224];  // [b][co][n][m]
__device__ __align__(16) uint32_t g_x1l[(size_t)BATCH * 32 * NSTA * 224];
__device__ __align__(16) uint32_t g_x2h[(size_t)BATCH * 64 * 80 * 568];    // [b][co][m][n]
__device__ __align__(16) uint32_t g_x2l[(size_t)BATCH * 64 * 80 * 568];
__device__ float g_x3[(size_t)BATCH * 128 * NSTA * 17];      // conv3 out FLAT fp32
__device__ float g_dinv[NSTA];
__device__ float g_normT[NSTA * NSTA];
__device__ float g_bufA[BATCH * NSTA * 64];
__device__ float g_bufB[BATCH * NSTA * 64];
__device__ float g_fc1p[8 * BATCH * 1280];
__device__ float g_fc1[BATCH * 1280];
__device__ float g_extra[BATCH * NSTA];
__device__ float g_z[BATCH * ZDIM];

// ---------------- bf16 / mma / cp.async helpers ----------------
__device__ __forceinline__ void split2(float v0, float v1, uint32_t& hw, uint32_t& lw) {
    __nv_bfloat16 h0 = __float2bfloat16(v0);
    __nv_bfloat16 h1 = __float2bfloat16(v1);
    float r0 = v0 - __bfloat162float(h0);
    float r1 = v1 - __bfloat162float(h1);
    __nv_bfloat16 l0 = __float2bfloat16(r0);
    __nv_bfloat16 l1 = __float2bfloat16(r1);
    hw = (uint32_t)__bfloat16_as_ushort(h0) | ((uint32_t)__bfloat16_as_ushort(h1) << 16);
    lw = (uint32_t)__bfloat16_as_ushort(l0) | ((uint32_t)__bfloat16_as_ushort(l1) << 16);
}

__device__ __forceinline__ void mmabf(float* c, const uint32_t* a, uint32_t b0, uint32_t b1) {
    asm volatile(
        "mma.sync.aligned.m16n8k16.row.col.f32.bf16.bf16.f32 "
        "{%0,%1,%2,%3},{%4,%5,%6,%7},{%8,%9},{%0,%1,%2,%3};"
        : "+f"(c[0]), "+f"(c[1]), "+f"(c[2]), "+f"(c[3])
        : "r"(a[0]), "r"(a[1]), "r"(a[2]), "r"(a[3]), "r"(b0), "r"(b1));
}

__device__ __forceinline__ void cpa16(uint32_t dst, const void* src) {
    asm volatile("cp.async.cg.shared.global [%0], [%1], 16;" :: "r"(dst), "l"(src) : "memory");
}
#define CPA_COMMIT() asm volatile("cp.async.commit_group;" ::: "memory")
#define CPA_WAIT1()  asm volatile("cp.async.wait_group 1;" ::: "memory")

// ---------------- weight prep: fp32 [CO][CI][125] -> packed bf16x2 hi/lo [CO][CI][64] ----
__global__ void k_wprep(const float* __restrict__ w, uint32_t* __restrict__ wh,
                        uint32_t* __restrict__ wl, int total) {
    int i = blockIdx.x * 256 + threadIdx.x;
    if (i >= total) return;
    int m = i & 63;
    int rest = i >> 6;  // co*CIN + ci
    const float* wr = w + (long)rest * 125;
    float v0 = (2 * m     < 125) ? wr[2 * m]     : 0.f;
    float v1 = (2 * m + 1 < 125) ? wr[2 * m + 1] : 0.f;
    uint32_t a, b;
    split2(v0, v1, a, b);
    wh[i] = a;
    wl[i] = b;
}

// ---------------- graph norm ----------------
__global__ void k_deg(const float* __restrict__ A, float* __restrict__ dinv) {
    int c = blockIdx.x;
    float s = 0.f;
    for (int r = threadIdx.x; r < NSTA; r += 64) s += A[r * NSTA + c];
    __shared__ float red[64];
    red[threadIdx.x] = s;
    __syncthreads();
    for (int o = 32; o > 0; o >>= 1) {
        if (threadIdx.x < o) red[threadIdx.x] += red[threadIdx.x + o];
        __syncthreads();
    }
    if (threadIdx.x == 0) dinv[c] = rsqrtf(red[0] + 1.0f);
}

__global__ void k_norm(const float* __restrict__ A, const float* __restrict__ dinv,
                       float* __restrict__ normT) {
    int c = blockIdx.x;
    float dc = dinv[c];
    for (int r = threadIdx.x; r < NSTA; r += 256) {
        float a = A[r * NSTA + c] + (r == c ? 1.0f : 0.0f);
        normT[c * NSTA + r] = dinv[r] * a * dc;
    }
}

// ---------------- conv1: CIN=3, all weights resident, no inner barriers ----------------
__global__ void __launch_bounds__(256, 2)
k_conv1n(const float* __restrict__ wav, const uint32_t* __restrict__ wgh,
         const uint32_t* __restrict__ wgl, const float* __restrict__ bias,
         uint32_t* __restrict__ oh, uint32_t* __restrict__ ol) {
    extern __shared__ uint32_t smu[];
    uint32_t* s_ih = smu;                 // 3*516
    uint32_t* s_il = smu + 3 * 516;
    uint32_t* s_wh = smu + 2 * 3 * 516;   // 3*2176 (ci-major blocks)
    uint32_t* s_wl = s_wh + 3 * 2176;
    const int b = blockIdx.x / NSTA, n = blockIdx.x % NSTA;
    const int tid = threadIdx.x, lane = tid & 31, wid = tid >> 5;
    const int wm = wid >> 2, wn = wid & 3;       // MW=2, NWC=4
    const int nbase = wn * 112;                  // WN=112, NG=14
    const int g = lane >> 2, k3 = lane & 3;

    for (int i = tid; i < 3 * 512; i += 256) {
        int ci = i / 512, m = i % 512;
        int t0 = 2 * m, t1 = t0 + 1;
        const float* base = wav + ((long)(b * NSTA + n)) * 3000 + ci;
        float v0 = (t0 < 1000) ? base[t0 * 3] : 0.f;
        float v1 = (t1 < 1000) ? base[t1 * 3] : 0.f;
        uint32_t hw, lw;
        split2(v0, v1, hw, lw);
        s_ih[ci * 516 + m] = hw;
        s_il[ci * 516 + m] = lw;
    }
    const uint4* wh4 = (const uint4*)wgh;
    const uint4* wl4 = (const uint4*)wgl;
    for (int i = tid; i < 1536; i += 256) {
        int co = i / 48, rr = i % 48, ci = rr >> 4, v = rr & 15;
        long src = ((long)co * 3 + ci) * 16 + v;
        *reinterpret_cast<uint4*>(s_wh + ci * 2176 + co * 68 + 4 * v) = wh4[src];
        *reinterpret_cast<uint4*>(s_wl + ci * 2176 + co * 68 + 4 * v) = wl4[src];
    }
    __syncthreads();

    float acc[14][4];
#pragma unroll
    for (int gg = 0; gg < 14; gg++)
#pragma unroll
        for (int q = 0; q < 4; q++) acc[gg][q] = 0.f;

    for (int ci = 0; ci < 3; ci++) {
        const uint32_t* swh = s_wh + ci * 2176;
        const uint32_t* swl = s_wl + ci * 2176;
        const uint32_t* bh = s_ih + ci * 516;
        const uint32_t* bl = s_il + ci * 516;
#pragma unroll
        for (int ks = 0; ks < 8; ks++) {
            uint32_t Ah[4], Al[4];
            {
                int co = wm * 16 + g;
                const uint32_t* p = swh + co * 68 + ks * 8 + k3;
                Ah[0] = p[0]; Ah[1] = p[8 * 68]; Ah[2] = p[4]; Ah[3] = p[8 * 68 + 4];
                const uint32_t* q = swl + co * 68 + ks * 8 + k3;
                Al[0] = q[0]; Al[1] = q[8 * 68]; Al[2] = q[4]; Al[3] = q[8 * 68 + 4];
            }
#pragma unroll
            for (int gg = 0; gg < 14; gg++) {
                int widx = nbase + gg * 8 + g + ks * 8 + k3;
                uint32_t b0h = bh[widx], b1h = bh[widx + 4];
                uint32_t b0l = bl[widx], b1l = bl[widx + 4];
                mmabf(acc[gg], Ah, b0h, b1h);
                mmabf(acc[gg], Al, b0h, b1h);
                mmabf(acc[gg], Ah, b0l, b1l);
            }
        }
    }

#pragma unroll
    for (int gg = 0; gg < 14; gg++) {
        int wo = nbase + gg * 8 + 2 * k3;
        int m = wo >> 1;
#pragma unroll
        for (int half = 0; half < 2; half++) {
            int co = wm * 16 + g + half * 8;
            float bb = bias[co];
            float v0 = acc[gg][half * 2 + 0] + bb;
            float v1 = acc[gg][half * 2 + 1] + bb;
            v0 = (wo < 438) ? fmaxf(v0, 0.f) : 0.f;
            v1 = (wo + 1 < 438) ? fmaxf(v1, 0.f) : 0.f;
            uint32_t hw, lw;
            split2(v0, v1, hw, lw);
            long idx = (((long)(b * 32 + co)) * NSTA + n) * 224 + m;
            oh[idx] = hw;
            ol[idx] = lw;
        }
    }
}

// ---------------- conv2: 2 stations/CTA, weights cp.async double-buffered ----------------
__global__ void __launch_bounds__(256, 1)
k_conv2n(const uint32_t* __restrict__ inh, const uint32_t* __restrict__ inl,
         const uint32_t* __restrict__ wgh, const uint32_t* __restrict__ wgl,
         const float* __restrict__ bias,
         uint32_t* __restrict__ oh, uint32_t* __restrict__ ol) {
    extern __shared__ uint32_t smu[];
    uint32_t* s_ih = smu;                 // 32*456
    uint32_t* s_il = smu + 14592;
    uint32_t* s_w  = smu + 29184;         // 2 bufs * (2hl * 64*68) = 17408
    const int b = blockIdx.x / 283, pr = blockIdx.x % 283;
    const int n0 = pr * 2;
    const int tid = threadIdx.x, lane = tid & 31, wid = tid >> 5;
    const int wm = wid >> 2, wn = wid & 3;
    const int st = wn >> 1, nbl = (wn & 1) * 80;   // station idx, local n-base (NG=10)
    const int g = lane >> 2, k3 = lane & 3;
    const uint32_t swb = (uint32_t)__cvta_generic_to_shared(s_w);
    const uint4* wh4 = (const uint4*)wgh;
    const uint4* wl4 = (const uint4*)wgl;

    // resident input: 32ci x 2st x 56 uint4 (hi & lo)
    {
        const uint4* ih4 = (const uint4*)inh;
        const uint4* il4 = (const uint4*)inl;
        const uint4 z = make_uint4(0, 0, 0, 0);
        for (int i = tid; i < 32 * 2 * 56; i += 256) {
            int v = i % 56, rr = i / 56;
            int s2 = rr & 1, ci = rr >> 1;
            int n = n0 + s2;
            uint4 a = z, c = z;
            if (n < NSTA) {
                long src = (((long)(b * 32 + ci)) * NSTA + n) * 56 + v;
                a = ih4[src];
                c = il4[src];
            }
            *reinterpret_cast<uint4*>(s_ih + ci * 456 + s2 * 228 + 4 * v) = a;
            *reinterpret_cast<uint4*>(s_il + ci * 456 + s2 * 228 + 4 * v) = c;
        }
    }

#define C2_ISSUE(CI, BUF) do {                                                     \
        _Pragma("unroll")                                                          \
        for (int t = 0; t < 8; t++) {                                              \
            int j = tid + t * 256;                                                 \
            int hl = j >> 10, co = (j >> 4) & 63, v = j & 15;                      \
            const uint4* src = (hl ? wl4 : wh4) + ((long)co * 32 + (CI)) * 16 + v; \
            cpa16(swb + ((BUF) * 8704 + hl * 4352 + co * 68 + 4 * v) * 4, src);    \
        }                                                                          \
    } while (0)

    float acc[2][10][4];
#pragma unroll
    for (int mf = 0; mf < 2; mf++)
#pragma unroll
        for (int gg = 0; gg < 10; gg++)
#pragma unroll
            for (int q = 0; q < 4; q++) acc[mf][gg][q] = 0.f;

    C2_ISSUE(0, 0);
    CPA_COMMIT();

    for (int ci = 0; ci < 32; ci++) {
        if (ci + 1 < 32) C2_ISSUE(ci + 1, (ci + 1) & 1);
        CPA_COMMIT();
        CPA_WAIT1();
        __syncthreads();
        const uint32_t* swh = s_w + (ci & 1) * 8704;
        const uint32_t* swl = swh + 4352;
        const uint32_t* bh = s_ih + ci * 456 + st * 228;
        const uint32_t* bl = s_il + ci * 456 + st * 228;
#pragma unroll
        for (int ks = 0; ks < 8; ks++) {
            uint32_t Ah[2][4], Al[2][4];
#pragma unroll
            for (int mf = 0; mf < 2; mf++) {
                int co = wm * 32 + mf * 16 + g;
                const uint32_t* p = swh + co * 68 + ks * 8 + k3;
                Ah[mf][0] = p[0]; Ah[mf][1] = p[8 * 68]; Ah[mf][2] = p[4]; Ah[mf][3] = p[8 * 68 + 4];
                const uint32_t* q = swl + co * 68 + ks * 8 + k3;
                Al[mf][0] = q[0]; Al[mf][1] = q[8 * 68]; Al[mf][2] = q[4]; Al[mf][3] = q[8 * 68 + 4];
            }
#pragma unroll
            for (int gg = 0; gg < 10; gg++) {
                int widx = nbl + gg * 8 + g + ks * 8 + k3;
                uint32_t b0h = bh[widx], b1h = bh[widx + 4];
                uint32_t b0l = bl[widx], b1l = bl[widx + 4];
#pragma unroll
                for (int mf = 0; mf < 2; mf++) {
                    mmabf(acc[mf][gg], Ah[mf], b0h, b1h);
                    mmabf(acc[mf][gg], Al[mf], b0h, b1h);
                    mmabf(acc[mf][gg], Ah[mf], b0l, b1l);
                }
            }
        }
        __syncthreads();   // WAR guard before buffer reuse
    }

    int n = n0 + st;
    if (n < NSTA) {
#pragma unroll
        for (int mf = 0; mf < 2; mf++) {
#pragma unroll
            for (int gg = 0; gg < 10; gg++) {
                int wo = nbl + gg * 8 + 2 * k3;
                int m = wo >> 1;
#pragma unroll
                for (int half = 0; half < 2; half++) {
                    int co = wm * 32 + mf * 16 + g + half * 8;
                    float bb = bias[co];
                    float v0 = acc[mf][gg][half * 2 + 0] + bb;
                    float v1 = acc[mf][gg][half * 2 + 1] + bb;
                    v0 = (wo < 157) ? fmaxf(v0, 0.f) : 0.f;
                    v1 = (wo + 1 < 157) ? fmaxf(v1, 0.f) : 0.f;
                    uint32_t hw, lw;
                    split2(v0, v1, hw, lw);
                    long idx = (((long)(b * 64 + co)) * 80 + m) * 568 + n;
                    oh[idx] = hw;
                    ol[idx] = lw;
                }
            }
        }
    }
#undef C2_ISSUE
}

// ---------------- conv3: cp.async double-buffered input + weights ----------------
__global__ void __launch_bounds__(256, 1)
k_conv3n(const uint32_t* __restrict__ x2h, const uint32_t* __restrict__ x2l,
         const uint32_t* __restrict__ wgh, const uint32_t* __restrict__ wgl,
         const float* __restrict__ bias, float* __restrict__ out) {
    extern __shared__ uint32_t smu[];
    uint32_t* s_p = smu;            // 2 bufs * (2hl * 64*72) = 18432
    uint32_t* s_w = smu + 18432;    // 2 bufs * (2hl * 128*68) = 34816
    const int cta = blockIdx.x;
    const int b = cta / 153, r = cta % 153;
    const int wo = r / 9, nt = r % 9;
    const int n0 = (nt == 8) ? 504 : nt * 64;
    const int tid = threadIdx.x, lane = tid & 31, wid = tid >> 5;
    const int wm = wid >> 1, wn = wid & 1;
    const int g = lane >> 2, k3 = lane & 3;
    const uint32_t spb = (uint32_t)__cvta_generic_to_shared(s_p);
    const uint32_t swb = (uint32_t)__cvta_generic_to_shared(s_w);
    const uint4* wh4 = (const uint4*)wgh;
    const uint4* wl4 = (const uint4*)wgl;
    const uint4* ph4 = (const uint4*)x2h;
    const uint4* pl4 = (const uint4*)x2l;
    const int nw4 = n0 >> 2;

#define C3_ISSUE(CI, BUF) do {                                                      \
        _Pragma("unroll")                                                           \
        for (int t = 0; t < 16; t++) {                                              \
            int j = tid + t * 256;                                                  \
            int hl = j >> 11, co = (j >> 4) & 127, v = j & 15;                      \
            const uint4* src = (hl ? wl4 : wh4) + ((long)co * 64 + (CI)) * 16 + v;  \
            cpa16(swb + ((BUF) * 17408 + hl * 8704 + co * 68 + 4 * v) * 4, src);    \
        }                                                                           \
        _Pragma("unroll")                                                           \
        for (int t = 0; t < 8; t++) {                                               \
            int j = tid + t * 256;                                                  \
            int hl = j >> 10, m = (j >> 4) & 63, v = j & 15;                        \
            long row = ((long)(b * 64 + (CI))) * 80 + wo + m;                       \
            const uint4* src = (hl ? pl4 : ph4) + row * 142 + nw4 + v;              \
            cpa16(spb + ((BUF) * 9216 + hl * 4608 + m * 72 + 4 * v) * 4, src);      \
        }                                                                           \
    } while (0)

    float acc[2][4][4];
#pragma unroll
    for (int mf = 0; mf < 2; mf++)
#pragma unroll
        for (int gg = 0; gg < 4; gg++)
#pragma unroll
            for (int q = 0; q < 4; q++) acc[mf][gg][q] = 0.f;

    C3_ISSUE(0, 0);
    CPA_COMMIT();

    for (int ci = 0; ci < 64; ci++) {
        if (ci + 1 < 64) C3_ISSUE(ci + 1, (ci + 1) & 1);
        CPA_COMMIT();
        CPA_WAIT1();
        __syncthreads();
        const uint32_t* swh = s_w + (ci & 1) * 17408;
        const uint32_t* swl = swh + 8704;
        const uint32_t* sph = s_p + (ci & 1) * 9216;
        const uint32_t* spl = sph + 4608;
#pragma unroll
        for (int ks = 0; ks < 8; ks++) {
            uint32_t Ah[2][4], Al[2][4];
#pragma unroll
            for (int mf = 0; mf < 2; mf++) {
                int co = wm * 32 + mf * 16 + g;
                const uint32_t* p = swh + co * 68 + ks * 8 + k3;
                Ah[mf][0] = p[0]; Ah[mf][1] = p[8 * 68]; Ah[mf][2] = p[4]; Ah[mf][3] = p[8 * 68 + 4];
                const uint32_t* q = swl + co * 68 + ks * 8 + k3;
                Al[mf][0] = q[0]; Al[mf][1] = q[8 * 68]; Al[mf][2] = q[4]; Al[mf][3] = q[8 * 68 + 4];
            }
#pragma unroll
            for (int gg = 0; gg < 4; gg++) {
                int base = (ks * 8 + k3) * 72 + wn * 32 + gg * 8 + g;
                uint32_t b0h = sph[base], b1h = sph[base + 4 * 72];
                uint32_t b0l = spl[base], b1l = spl[base + 4 * 72];
#pragma unroll
                for (int mf = 0; mf < 2; mf++) {
                    mmabf(acc[mf][gg], Ah[mf], b0h, b1h);
                    mmabf(acc[mf][gg], Al[mf], b0h, b1h);
                    mmabf(acc[mf][gg], Ah[mf], b0l, b1l);
                }
            }
        }
        __syncthreads();   // WAR guard
    }

#pragma unroll
    for (int mf = 0; mf < 2; mf++) {
#pragma unroll
        for (int gg = 0; gg < 4; gg++) {
#pragma unroll
            for (int q = 0; q < 4; q++) {
                int co = wm * 32 + mf * 16 + g + ((q >> 1) << 3);
                int n = n0 + wn * 32 + gg * 8 + 2 * k3 + (q & 1);
                if (n < NSTA) {
                    float v = fmaxf(acc[mf][gg][q] + bias[co], 0.f);
                    out[(((long)(b * 128 + co)) * NSTA + n) * 17 + wo] = v;
                }
            }
        }
    }
#undef C3_ISSUE
}

// ---------------- GCN1 x@W on raw-reshape feature windows ----------------
__global__ void k_xw_feat(const float* __restrict__ x3, const float* __restrict__ wg,
                          float* __restrict__ h) {
    __shared__ float srow[4 * FEAT];
    int b = blockIdx.x / 142, ng = blockIdx.x % 142;
    int n0 = ng * 4;
    int tid = threadIdx.x;
    for (int i = tid; i < 4 * FEAT; i += 256) {
        int j = i / FEAT, k = i % FEAT;
        int n = n0 + j;
        srow[i] = (n < NSTA) ? x3[((long)(b * NSTA + n)) * FEAT + k] : 0.f;
    }
    __syncthreads();
    int j = tid >> 6, o = tid & 63;
    int n = n0 + j;
    if (n >= NSTA) return;
    const float* sr = srow + j * FEAT;
    float acc = 0.f;
    for (int k = 0; k < FEAT; k++) acc += sr[k] * wg[k * 64 + o];
    h[((long)(b * NSTA + n)) * 64 + o] = acc;
}

__global__ void k_xw64(const float* __restrict__ x, const float* __restrict__ w,
                       float* __restrict__ h) {
    __shared__ float srow[64];
    long bs = blockIdx.x;
    int tid = threadIdx.x;
    srow[tid] = x[bs * 64 + tid];
    __syncthreads();
    float acc = 0.f;
    for (int k = 0; k < 64; k++) acc += srow[k] * w[k * 64 + tid];
    h[bs * 64 + tid] = acc;
}

template <int ACT>  // 0 = relu, 1 = tanh
__global__ void k_agg(const float* __restrict__ h, const float* __restrict__ normT,
                      const float* __restrict__ bias, float* __restrict__ out) {
    __shared__ float sn[4 * NSTA];
    int b = blockIdx.x / 142, cg = blockIdx.x % 142;
    int c0 = cg * 4;
    int tid = threadIdx.x;  // 64
    for (int i = tid; i < 4 * NSTA; i += 64) {
        int cc = i / NSTA, rr = i % NSTA;
        int c = c0 + cc;
        sn[i] = (c < NSTA) ? normT[c * NSTA + rr] : 0.f;
    }
    __syncthreads();
    float bv = bias[tid];
    float acc[4] = {bv, bv, bv, bv};
    const float* hb = h + (long)b * NSTA * 64;
    for (int rr = 0; rr < NSTA; rr++) {
        float hv = hb[rr * 64 + tid];
#pragma unroll
        for (int q = 0; q < 4; q++) acc[q] += sn[q * NSTA + rr] * hv;
    }
#pragma unroll
    for (int q = 0; q < 4; q++) {
        int c = c0 + q;
        if (c < NSTA) {
            float v = ACT ? tanhf(acc[q]) : fmaxf(acc[q], 0.f);
            out[((long)b * NSTA + c) * 64 + tid] = v;
        }
    }
}

// ---------------- fc1 ----------------
__global__ void k_fc1_part(const float* __restrict__ x, const float* __restrict__ w,
                           float* __restrict__ part) {
    __shared__ float sx[16 * 512];
    int o = blockIdx.x * 128 + threadIdx.x;
    int k0 = blockIdx.y * 4520, k1 = k0 + 4520;
    float acc[16] = {};
    for (int kc = k0; kc < k1; kc += 512) {
        int len = min(512, k1 - kc);
        __syncthreads();
        for (int i = threadIdx.x; i < 16 * len; i += 128) {
            int bb = i / len, kk = i % len;
            sx[bb * 512 + kk] = x[bb * FLAT + kc + kk];
        }
        __syncthreads();
        for (int kk = 0; kk < len; kk++) {
            float wv = w[(long)(kc + kk) * 1280 + o];
#pragma unroll
            for (int bb = 0; bb < 16; bb++) acc[bb] += sx[bb * 512 + kk] * wv;
        }
    }
    for (int bb = 0; bb < 16; bb++) part[(blockIdx.y * 16 + bb) * 1280 + o] = acc[bb];
}

__global__ void k_fc1_fin(const float* __restrict__ part, const float* __restrict__ bias,
                          float* __restrict__ fc1) {
    int idx = blockIdx.x * blockDim.x + threadIdx.x;
    if (idx < 16 * 1280) {
        int b = idx / 1280, o = idx % 1280;
        float s = bias[o];
        for (int ks = 0; ks < 8; ks++) s += part[(ks * 16 + b) * 1280 + o];
        fc1[idx] = fmaxf(s, 0.f);
    }
}

// ---------------- extra / z / heads ----------------
__global__ void k_extra(const float* __restrict__ mv, const float* __restrict__ w,
                        const float* __restrict__ bias, float* __restrict__ out) {
    __shared__ float sx[NSTA];
    int b = blockIdx.x;
    for (int i = threadIdx.x; i < NSTA; i += blockDim.x) sx[i] = mv[b * NSTA + i];
    __syncthreads();
    int j = threadIdx.x;
    if (j < NSTA) {
        float acc = bias[j];
        for (int i = 0; i < NSTA; i++) acc += sx[i] * w[i * NSTA + j];
        out[b * NSTA + j] = fmaxf(acc, 0.f);
    }
}

__global__ void k_buildz(const float* __restrict__ fc1, const float* __restrict__ meta,
                         const float* __restrict__ extra, float* __restrict__ z) {
    int b = blockIdx.x;
    for (int i = threadIdx.x; i < ZDIM; i += blockDim.x) {
        float v;
        if (i < 1280)      v = fc1[b * 1280 + i];
        else if (i < 1285) v = meta[b * 5 + (i - 1280)];
        else               v = extra[b * NSTA + (i - 1285)];
        z[b * ZDIM + i] = v;
    }
}

__global__ void k_heads(const float* __restrict__ z,
                        const float* w0, const float* b0, const float* w1, const float* b1,
                        const float* w2, const float* b2, const float* w3, const float* b3,
                        const float* w4, const float* b4, float* __restrict__ out) {
    extern __shared__ float sz[];  // 16 * 1850
    const float* ws[5] = {w0, w1, w2, w3, w4};
    const float* bs[5] = {b0, b1, b2, b3, b4};
    int h = blockIdx.y;
    const float* w = ws[h];
    const float* bias = bs[h];
    int tid = threadIdx.x;
    for (int i = tid; i < 16 * ZDIM; i += 128) sz[i] = z[i];
    __syncthreads();
    int j = blockIdx.x * 128 + tid;
    if (j >= NSTA) return;
    float acc[16] = {};
    for (int k = 0; k < ZDIM; k++) {
        float wv = w[k * NSTA + j];
#pragma unroll
        for (int b = 0; b < 16; b++) acc[b] += sz[b * ZDIM + k] * wv;
    }
    float bb = bias[j];
    for (int b = 0; b < 16; b++) out[(h * 16 + b) * NSTA + j] = acc[b] + bb;
}

// ---------------- launch ----------------
extern "C" void kernel_launch(void* const* d_in, const int* in_sizes, int n_in,
                              void* d_out, int out_size) {
    const float* wav  = (const float*)d_in[0];
    const float* A    = (const float*)d_in[2];
    const float* meta = (const float*)d_in[3];
    const float* mv   = (const float*)d_in[4];
    const float* w1 = (const float*)d_in[5];  const float* b1 = (const float*)d_in[6];
    const float* w2 = (const float*)d_in[7];  const float* b2 = (const float*)d_in[8];
    const float* w3 = (const float*)d_in[9];  const float* b3 = (const float*)d_in[10];
    const float* wg1 = (const float*)d_in[11]; const float* bg1 = (const float*)d_in[12];
    const float* wg2 = (const float*)d_in[13]; const float* bg2 = (const float*)d_in[14];
    const float* wfe = (const float*)d_in[15]; const float* bfe = (const float*)d_in[16];
    const float* wf1 = (const float*)d_in[17]; const float* bf1 = (const float*)d_in[18];
    const float* wpga = (const float*)d_in[19]; const float* bpga = (const float*)d_in[20];
    const float* wpgv = (const float*)d_in[21]; const float* bpgv = (const float*)d_in[22];
    const float* ws03 = (const float*)d_in[23]; const float* bs03 = (const float*)d_in[24];
    const float* ws10 = (const float*)d_in[25]; const float* bs10 = (const float*)d_in[26];
    const float* ws30 = (const float*)d_in[27]; const float* bs30 = (const float*)d_in[28];
    float* out = (float*)d_out;

    uint32_t *pw1h, *pw1l, *pw2h, *pw2l, *pw3h, *pw3l;
    uint32_t *px1h, *px1l, *px2h, *px2l;
    float *px3, *pdinv, *pnorm, *pA, *pB, *ppart, *pfc1, *pextra, *pz;
    cudaGetSymbolAddress((void**)&pw1h, g_w1h);
    cudaGetSymbolAddress((void**)&pw1l, g_w1l);
    cudaGetSymbolAddress((void**)&pw2h, g_w2h);
    cudaGetSymbolAddress((void**)&pw2l, g_w2l);
    cudaGetSymbolAddress((void**)&pw3h, g_w3h);
    cudaGetSymbolAddress((void**)&pw3l, g_w3l);
    cudaGetSymbolAddress((void**)&px1h, g_x1h);
    cudaGetSymbolAddress((void**)&px1l, g_x1l);
    cudaGetSymbolAddress((void**)&px2h, g_x2h);
    cudaGetSymbolAddress((void**)&px2l, g_x2l);
    cudaGetSymbolAddress((void**)&px3, g_x3);
    cudaGetSymbolAddress((void**)&pdinv, g_dinv);
    cudaGetSymbolAddress((void**)&pnorm, g_normT);
    cudaGetSymbolAddress((void**)&pA, g_bufA);
    cudaGetSymbolAddress((void**)&pB, g_bufB);
    cudaGetSymbolAddress((void**)&ppart, g_fc1p);
    cudaGetSymbolAddress((void**)&pfc1, g_fc1);
    cudaGetSymbolAddress((void**)&pextra, g_extra);
    cudaGetSymbolAddress((void**)&pz, g_z);

    const int SM1 = (2 * 3 * 516 + 2 * 3 * 32 * 68) * 4;     // 64,608
    const int SM2 = (2 * 32 * 456 + 2 * 2 * 64 * 68) * 4;    // 186,368
    const int SM3 = (2 * 2 * 64 * 72 + 2 * 2 * 128 * 68) * 4; // 212,992
    const int SMH = 16 * ZDIM * 4;                           // 118,400
    cudaFuncSetAttribute(k_conv1n, cudaFuncAttributeMaxDynamicSharedMemorySize, SM1);
    cudaFuncSetAttribute(k_conv2n, cudaFuncAttributeMaxDynamicSharedMemorySize, SM2);
    cudaFuncSetAttribute(k_conv3n, cudaFuncAttributeMaxDynamicSharedMemorySize, SM3);
    cudaFuncSetAttribute(k_heads, cudaFuncAttributeMaxDynamicSharedMemorySize, SMH);

    k_wprep<<<(32 * 3 * 64 + 255) / 256, 256>>>(w1, pw1h, pw1l, 32 * 3 * 64);
    k_wprep<<<(64 * 32 * 64 + 255) / 256, 256>>>(w2, pw2h, pw2l, 64 * 32 * 64);
    k_wprep<<<(128 * 64 * 64 + 255) / 256, 256>>>(w3, pw3h, pw3l, 128 * 64 * 64);

    k_deg<<<NSTA, 64>>>(A, pdinv);
    k_norm<<<NSTA, 256>>>(A, pdinv, pnorm);

    k_conv1n<<<BATCH * NSTA, 256, SM1>>>(wav, pw1h, pw1l, b1, px1h, px1l);
    k_conv2n<<<BATCH * 283, 256, SM2>>>(px1h, px1l, pw2h, pw2l, b2, px2h, px2l);
    k_conv3n<<<BATCH * 17 * 9, 256, SM3>>>(px2h, px2l, pw3h, pw3l, b3, px3);

    k_xw_feat<<<BATCH * 142, 256>>>(px3, wg1, pA);
    k_agg<0><<<BATCH * 142, 64>>>(pA, pnorm, bg1, pB);
    k_xw64<<<BATCH * NSTA, 64>>>(pB, wg2, pA);
    k_agg<1><<<BATCH * 142, 64>>>(pA, pnorm, bg2, pB);

    k_fc1_part<<<dim3(10, 8), 128>>>(pB, wf1, ppart);
    k_fc1_fin<<<80, 256>>>(ppart, bf1, pfc1);
    k_extra<<<BATCH, 576>>>(mv, wfe, bfe, pextra);
    k_buildz<<<BATCH, 256>>>(pfc1, meta, pextra, pz);

    k_heads<<<dim3(5, 5), 128, SMH>>>(pz, wpga, bpga, wpgv, bpgv, ws03, bs03,
                                      ws10, bs10, ws30, bs30, out);
}

// round 15
// speedup vs baseline: 1.0472x; 1.0027x over previous
#include <cuda_runtime.h>
#include <cuda_bf16.h>
#include <math.h>
#include <stdint.h>

// ---------------- problem constants ----------------
#define BATCH 16
#define NSTA  565
#define FEAT  2176          // 128*17
#define FLAT  36160         // 565*64
#define ZDIM  1850          // 1280 + 5 + 565

// ---------------- scratch (no cudaMalloc allowed) ----------------
__device__ __align__(16) uint32_t g_w1h[32 * 3 * 64],   g_w1l[32 * 3 * 64];
__device__ __align__(16) uint32_t g_w2h[64 * 32 * 64],  g_w2l[64 * 32 * 64];
__device__ __align__(16) uint32_t g_w3h[128 * 64 * 64], g_w3l[128 * 64 * 64];
__device__ __align__(16) uint32_t g_x1h[(size_t)BATCH * 32 * NSTA * 224];  // [b][co][n][m]
__device__ __align__(16) uint32_t g_x1l[(size_t)BATCH * 32 * NSTA * 224];
__device__ __align__(16) uint32_t g_x2h[(size_t)BATCH * 64 * 80 * 568];    // [b][co][m][n]
__device__ __align__(16) uint32_t g_x2l[(size_t)BATCH * 64 * 80 * 568];
__device__ float g_x3[(size_t)BATCH * 128 * NSTA * 17];      // conv3 out FLAT fp32
__device__ float g_dinv[NSTA];
__device__ float g_normT[NSTA * NSTA];
__device__ float g_bufA[BATCH * NSTA * 64];
__device__ float g_bufB[BATCH * NSTA * 64];
__device__ float g_fc1p[8 * BATCH * 1280];
__device__ float g_fc1[BATCH * 1280];
__device__ float g_extra[BATCH * NSTA];
__device__ float g_z[BATCH * ZDIM];

// ---------------- bf16 / mma / cp.async helpers ----------------
__device__ __forceinline__ void split2(float v0, float v1, uint32_t& hw, uint32_t& lw) {
    __nv_bfloat16 h0 = __float2bfloat16(v0);
    __nv_bfloat16 h1 = __float2bfloat16(v1);
    float r0 = v0 - __bfloat162float(h0);
    float r1 = v1 - __bfloat162float(h1);
    __nv_bfloat16 l0 = __float2bfloat16(r0);
    __nv_bfloat16 l1 = __float2bfloat16(r1);
    hw = (uint32_t)__bfloat16_as_ushort(h0) | ((uint32_t)__bfloat16_as_ushort(h1) << 16);
    lw = (uint32_t)__bfloat16_as_ushort(l0) | ((uint32_t)__bfloat16_as_ushort(l1) << 16);
}

__device__ __forceinline__ void mmabf(float* c, const uint32_t* a, uint32_t b0, uint32_t b1) {
    asm volatile(
        "mma.sync.aligned.m16n8k16.row.col.f32.bf16.bf16.f32 "
        "{%0,%1,%2,%3},{%4,%5,%6,%7},{%8,%9},{%0,%1,%2,%3};"
        : "+f"(c[0]), "+f"(c[1]), "+f"(c[2]), "+f"(c[3])
        : "r"(a[0]), "r"(a[1]), "r"(a[2]), "r"(a[3]), "r"(b0), "r"(b1));
}

__device__ __forceinline__ void cpa16(uint32_t dst, const void* src) {
    asm volatile("cp.async.cg.shared.global [%0], [%1], 16;" :: "r"(dst), "l"(src) : "memory");
}
#define CPA_COMMIT() asm volatile("cp.async.commit_group;" ::: "memory")
#define CPA_WAIT1()  asm volatile("cp.async.wait_group 1;" ::: "memory")

// ---------------- weight prep: fp32 [CO][CI][125] -> packed bf16x2 hi/lo [CO][CI][64] ----
__global__ void k_wprep(const float* __restrict__ w, uint32_t* __restrict__ wh,
                        uint32_t* __restrict__ wl, int total) {
    int i = blockIdx.x * 256 + threadIdx.x;
    if (i >= total) return;
    int m = i & 63;
    int rest = i >> 6;  // co*CIN + ci
    const float* wr = w + (long)rest * 125;
    float v0 = (2 * m     < 125) ? wr[2 * m]     : 0.f;
    float v1 = (2 * m + 1 < 125) ? wr[2 * m + 1] : 0.f;
    uint32_t a, b;
    split2(v0, v1, a, b);
    wh[i] = a;
    wl[i] = b;
}

// ---------------- graph norm ----------------
__global__ void k_deg(const float* __restrict__ A, float* __restrict__ dinv) {
    int c = blockIdx.x;
    float s = 0.f;
    for (int r = threadIdx.x; r < NSTA; r += 64) s += A[r * NSTA + c];
    __shared__ float red[64];
    red[threadIdx.x] = s;
    __syncthreads();
    for (int o = 32; o > 0; o >>= 1) {
        if (threadIdx.x < o) red[threadIdx.x] += red[threadIdx.x + o];
        __syncthreads();
    }
    if (threadIdx.x == 0) dinv[c] = rsqrtf(red[0] + 1.0f);
}

__global__ void k_norm(const float* __restrict__ A, const float* __restrict__ dinv,
                       float* __restrict__ normT) {
    int c = blockIdx.x;
    float dc = dinv[c];
    for (int r = threadIdx.x; r < NSTA; r += 256) {
        float a = A[r * NSTA + c] + (r == c ? 1.0f : 0.0f);
        normT[c * NSTA + r] = dinv[r] * a * dc;
    }
}

// ---------------- conv1: CIN=3, all weights resident, no inner barriers ----------------
__global__ void __launch_bounds__(256, 2)
k_conv1n(const float* __restrict__ wav, const uint32_t* __restrict__ wgh,
         const uint32_t* __restrict__ wgl, const float* __restrict__ bias,
         uint32_t* __restrict__ oh, uint32_t* __restrict__ ol) {
    extern __shared__ uint32_t smu[];
    uint32_t* s_ih = smu;                 // 3*516
    uint32_t* s_il = smu + 3 * 516;
    uint32_t* s_wh = smu + 2 * 3 * 516;   // 3*2176 (ci-major blocks)
    uint32_t* s_wl = s_wh + 3 * 2176;
    const int b = blockIdx.x / NSTA, n = blockIdx.x % NSTA;
    const int tid = threadIdx.x, lane = tid & 31, wid = tid >> 5;
    const int wm = wid >> 2, wn = wid & 3;       // MW=2, NWC=4
    const int nbase = wn * 112;                  // WN=112, NG=14
    const int g = lane >> 2, k3 = lane & 3;

    for (int i = tid; i < 3 * 512; i += 256) {
        int ci = i / 512, m = i % 512;
        int t0 = 2 * m, t1 = t0 + 1;
        const float* base = wav + ((long)(b * NSTA + n)) * 3000 + ci;
        float v0 = (t0 < 1000) ? base[t0 * 3] : 0.f;
        float v1 = (t1 < 1000) ? base[t1 * 3] : 0.f;
        uint32_t hw, lw;
        split2(v0, v1, hw, lw);
        s_ih[ci * 516 + m] = hw;
        s_il[ci * 516 + m] = lw;
    }
    const uint4* wh4 = (const uint4*)wgh;
    const uint4* wl4 = (const uint4*)wgl;
    for (int i = tid; i < 1536; i += 256) {
        int co = i / 48, rr = i % 48, ci = rr >> 4, v = rr & 15;
        long src = ((long)co * 3 + ci) * 16 + v;
        *reinterpret_cast<uint4*>(s_wh + ci * 2176 + co * 68 + 4 * v) = wh4[src];
        *reinterpret_cast<uint4*>(s_wl + ci * 2176 + co * 68 + 4 * v) = wl4[src];
    }
    __syncthreads();

    float acc[14][4];
#pragma unroll
    for (int gg = 0; gg < 14; gg++)
#pragma unroll
        for (int q = 0; q < 4; q++) acc[gg][q] = 0.f;

    for (int ci = 0; ci < 3; ci++) {
        const uint32_t* swh = s_wh + ci * 2176;
        const uint32_t* swl = s_wl + ci * 2176;
        const uint32_t* bh = s_ih + ci * 516;
        const uint32_t* bl = s_il + ci * 516;
#pragma unroll
        for (int ks = 0; ks < 8; ks++) {
            uint32_t Ah[4], Al[4];
            {
                int co = wm * 16 + g;
                const uint32_t* p = swh + co * 68 + ks * 8 + k3;
                Ah[0] = p[0]; Ah[1] = p[8 * 68]; Ah[2] = p[4]; Ah[3] = p[8 * 68 + 4];
                const uint32_t* q = swl + co * 68 + ks * 8 + k3;
                Al[0] = q[0]; Al[1] = q[8 * 68]; Al[2] = q[4]; Al[3] = q[8 * 68 + 4];
            }
#pragma unroll
            for (int gg = 0; gg < 14; gg++) {
                int widx = nbase + gg * 8 + g + ks * 8 + k3;
                uint32_t b0h = bh[widx], b1h = bh[widx + 4];
                uint32_t b0l = bl[widx], b1l = bl[widx + 4];
                mmabf(acc[gg], Ah, b0h, b1h);
                mmabf(acc[gg], Al, b0h, b1h);
                mmabf(acc[gg], Ah, b0l, b1l);
            }
        }
    }

#pragma unroll
    for (int gg = 0; gg < 14; gg++) {
        int wo = nbase + gg * 8 + 2 * k3;
        int m = wo >> 1;
#pragma unroll
        for (int half = 0; half < 2; half++) {
            int co = wm * 16 + g + half * 8;
            float bb = bias[co];
            float v0 = acc[gg][half * 2 + 0] + bb;
            float v1 = acc[gg][half * 2 + 1] + bb;
            v0 = (wo < 438) ? fmaxf(v0, 0.f) : 0.f;
            v1 = (wo + 1 < 438) ? fmaxf(v1, 0.f) : 0.f;
            uint32_t hw, lw;
            split2(v0, v1, hw, lw);
            long idx = (((long)(b * 32 + co)) * NSTA + n) * 224 + m;
            oh[idx] = hw;
            ol[idx] = lw;
        }
    }
}

// ---------------- conv2: 2 stations/CTA, weights cp.async double-buffered ----------------
__global__ void __launch_bounds__(256, 1)
k_conv2n(const uint32_t* __restrict__ inh, const uint32_t* __restrict__ inl,
         const uint32_t* __restrict__ wgh, const uint32_t* __restrict__ wgl,
         const float* __restrict__ bias,
         uint32_t* __restrict__ oh, uint32_t* __restrict__ ol) {
    extern __shared__ uint32_t smu[];
    uint32_t* s_ih = smu;                 // 32*456
    uint32_t* s_il = smu + 14592;
    uint32_t* s_w  = smu + 29184;         // 2 bufs * (2hl * 64*68) = 17408
    const int b = blockIdx.x / 283, pr = blockIdx.x % 283;
    const int n0 = pr * 2;
    const int tid = threadIdx.x, lane = tid & 31, wid = tid >> 5;
    const int wm = wid >> 2, wn = wid & 3;
    const int st = wn >> 1, nbl = (wn & 1) * 80;   // station idx, local n-base (NG=10)
    const int g = lane >> 2, k3 = lane & 3;
    const uint32_t swb = (uint32_t)__cvta_generic_to_shared(s_w);
    const uint4* wh4 = (const uint4*)wgh;
    const uint4* wl4 = (const uint4*)wgl;

    // resident input: 32ci x 2st x 56 uint4 (hi & lo)
    {
        const uint4* ih4 = (const uint4*)inh;
        const uint4* il4 = (const uint4*)inl;
        const uint4 z = make_uint4(0, 0, 0, 0);
        for (int i = tid; i < 32 * 2 * 56; i += 256) {
            int v = i % 56, rr = i / 56;
            int s2 = rr & 1, ci = rr >> 1;
            int n = n0 + s2;
            uint4 a = z, c = z;
            if (n < NSTA) {
                long src = (((long)(b * 32 + ci)) * NSTA + n) * 56 + v;
                a = ih4[src];
                c = il4[src];
            }
            *reinterpret_cast<uint4*>(s_ih + ci * 456 + s2 * 228 + 4 * v) = a;
            *reinterpret_cast<uint4*>(s_il + ci * 456 + s2 * 228 + 4 * v) = c;
        }
    }

#define C2_ISSUE(CI, BUF) do {                                                     \
        _Pragma("unroll")                                                          \
        for (int t = 0; t < 8; t++) {                                              \
            int j = tid + t * 256;                                                 \
            int hl = j >> 10, co = (j >> 4) & 63, v = j & 15;                      \
            const uint4* src = (hl ? wl4 : wh4) + ((long)co * 32 + (CI)) * 16 + v; \
            cpa16(swb + ((BUF) * 8704 + hl * 4352 + co * 68 + 4 * v) * 4, src);    \
        }                                                                          \
    } while (0)

    float acc[2][10][4];
#pragma unroll
    for (int mf = 0; mf < 2; mf++)
#pragma unroll
        for (int gg = 0; gg < 10; gg++)
#pragma unroll
            for (int q = 0; q < 4; q++) acc[mf][gg][q] = 0.f;

    C2_ISSUE(0, 0);
    CPA_COMMIT();

    for (int ci = 0; ci < 32; ci++) {
        if (ci + 1 < 32) C2_ISSUE(ci + 1, (ci + 1) & 1);
        CPA_COMMIT();
        CPA_WAIT1();
        __syncthreads();
        const uint32_t* swh = s_w + (ci & 1) * 8704;
        const uint32_t* swl = swh + 4352;
        const uint32_t* bh = s_ih + ci * 456 + st * 228;
        const uint32_t* bl = s_il + ci * 456 + st * 228;
#pragma unroll
        for (int ks = 0; ks < 8; ks++) {
            uint32_t Ah[2][4], Al[2][4];
#pragma unroll
            for (int mf = 0; mf < 2; mf++) {
                int co = wm * 32 + mf * 16 + g;
                const uint32_t* p = swh + co * 68 + ks * 8 + k3;
                Ah[mf][0] = p[0]; Ah[mf][1] = p[8 * 68]; Ah[mf][2] = p[4]; Ah[mf][3] = p[8 * 68 + 4];
                const uint32_t* q = swl + co * 68 + ks * 8 + k3;
                Al[mf][0] = q[0]; Al[mf][1] = q[8 * 68]; Al[mf][2] = q[4]; Al[mf][3] = q[8 * 68 + 4];
            }
#pragma unroll
            for (int gg = 0; gg < 10; gg++) {
                int widx = nbl + gg * 8 + g + ks * 8 + k3;
                uint32_t b0h = bh[widx], b1h = bh[widx + 4];
                uint32_t b0l = bl[widx], b1l = bl[widx + 4];
#pragma unroll
                for (int mf = 0; mf < 2; mf++) {
                    mmabf(acc[mf][gg], Ah[mf], b0h, b1h);
                    mmabf(acc[mf][gg], Al[mf], b0h, b1h);
                    mmabf(acc[mf][gg], Ah[mf], b0l, b1l);
                }
            }
        }
        __syncthreads();   // WAR guard before buffer reuse
    }

    int n = n0 + st;
    if (n < NSTA) {
#pragma unroll
        for (int mf = 0; mf < 2; mf++) {
#pragma unroll
            for (int gg = 0; gg < 10; gg++) {
                int wo = nbl + gg * 8 + 2 * k3;
                int m = wo >> 1;
#pragma unroll
                for (int half = 0; half < 2; half++) {
                    int co = wm * 32 + mf * 16 + g + half * 8;
                    float bb = bias[co];
                    float v0 = acc[mf][gg][half * 2 + 0] + bb;
                    float v1 = acc[mf][gg][half * 2 + 1] + bb;
                    v0 = (wo < 157) ? fmaxf(v0, 0.f) : 0.f;
                    v1 = (wo + 1 < 157) ? fmaxf(v1, 0.f) : 0.f;
                    uint32_t hw, lw;
                    split2(v0, v1, hw, lw);
                    long idx = (((long)(b * 64 + co)) * 80 + m) * 568 + n;
                    oh[idx] = hw;
                    ol[idx] = lw;
                }
            }
        }
    }
#undef C2_ISSUE
}

// ---------------- conv3: cp.async double-buffered input + weights ----------------
__global__ void __launch_bounds__(256, 1)
k_conv3n(const uint32_t* __restrict__ x2h, const uint32_t* __restrict__ x2l,
         const uint32_t* __restrict__ wgh, const uint32_t* __restrict__ wgl,
         const float* __restrict__ bias, float* __restrict__ out) {
    extern __shared__ uint32_t smu[];
    uint32_t* s_p = smu;            // 2 bufs * (2hl * 64*72) = 18432
    uint32_t* s_w = smu + 18432;    // 2 bufs * (2hl * 128*68) = 34816
    const int cta = blockIdx.x;
    const int b = cta / 153, r = cta % 153;
    const int wo = r / 9, nt = r % 9;
    const int n0 = (nt == 8) ? 504 : nt * 64;
    const int tid = threadIdx.x, lane = tid & 31, wid = tid >> 5;
    const int wm = wid >> 1, wn = wid & 1;
    const int g = lane >> 2, k3 = lane & 3;
    const uint32_t spb = (uint32_t)__cvta_generic_to_shared(s_p);
    const uint32_t swb = (uint32_t)__cvta_generic_to_shared(s_w);
    const uint4* wh4 = (const uint4*)wgh;
    const uint4* wl4 = (const uint4*)wgl;
    const uint4* ph4 = (const uint4*)x2h;
    const uint4* pl4 = (const uint4*)x2l;
    const int nw4 = n0 >> 2;

#define C3_ISSUE(CI, BUF) do {                                                      \
        _Pragma("unroll")                                                           \
        for (int t = 0; t < 16; t++) {                                              \
            int j = tid + t * 256;                                                  \
            int hl = j >> 11, co = (j >> 4) & 127, v = j & 15;                      \
            const uint4* src = (hl ? wl4 : wh4) + ((long)co * 64 + (CI)) * 16 + v;  \
            cpa16(swb + ((BUF) * 17408 + hl * 8704 + co * 68 + 4 * v) * 4, src);    \
        }                                                                           \
        _Pragma("unroll")                                                           \
        for (int t = 0; t < 8; t++) {                                               \
            int j = tid + t * 256;                                                  \
            int hl = j >> 10, m = (j >> 4) & 63, v = j & 15;                        \
            long row = ((long)(b * 64 + (CI))) * 80 + wo + m;                       \
            const uint4* src = (hl ? pl4 : ph4) + row * 142 + nw4 + v;              \
            cpa16(spb + ((BUF) * 9216 + hl * 4608 + m * 72 + 4 * v) * 4, src);      \
        }                                                                           \
    } while (0)

    float acc[2][4][4];
#pragma unroll
    for (int mf = 0; mf < 2; mf++)
#pragma unroll
        for (int gg = 0; gg < 4; gg++)
#pragma unroll
            for (int q = 0; q < 4; q++) acc[mf][gg][q] = 0.f;

    C3_ISSUE(0, 0);
    CPA_COMMIT();

    for (int ci = 0; ci < 64; ci++) {
        if (ci + 1 < 64) C3_ISSUE(ci + 1, (ci + 1) & 1);
        CPA_COMMIT();
        CPA_WAIT1();
        __syncthreads();
        const uint32_t* swh = s_w + (ci & 1) * 17408;
        const uint32_t* swl = swh + 8704;
        const uint32_t* sph = s_p + (ci & 1) * 9216;
        const uint32_t* spl = sph + 4608;
#pragma unroll
        for (int ks = 0; ks < 8; ks++) {
            uint32_t Ah[2][4], Al[2][4];
#pragma unroll
            for (int mf = 0; mf < 2; mf++) {
                int co = wm * 32 + mf * 16 + g;
                const uint32_t* p = swh + co * 68 + ks * 8 + k3;
                Ah[mf][0] = p[0]; Ah[mf][1] = p[8 * 68]; Ah[mf][2] = p[4]; Ah[mf][3] = p[8 * 68 + 4];
                const uint32_t* q = swl + co * 68 + ks * 8 + k3;
                Al[mf][0] = q[0]; Al[mf][1] = q[8 * 68]; Al[mf][2] = q[4]; Al[mf][3] = q[8 * 68 + 4];
            }
#pragma unroll
            for (int gg = 0; gg < 4; gg++) {
                int base = (ks * 8 + k3) * 72 + wn * 32 + gg * 8 + g;
                uint32_t b0h = sph[base], b1h = sph[base + 4 * 72];
                uint32_t b0l = spl[base], b1l = spl[base + 4 * 72];
#pragma unroll
                for (int mf = 0; mf < 2; mf++) {
                    mmabf(acc[mf][gg], Ah[mf], b0h, b1h);
                    mmabf(acc[mf][gg], Al[mf], b0h, b1h);
                    mmabf(acc[mf][gg], Ah[mf], b0l, b1l);
                }
            }
        }
        __syncthreads();   // WAR guard
    }

#pragma unroll
    for (int mf = 0; mf < 2; mf++) {
#pragma unroll
        for (int gg = 0; gg < 4; gg++) {
#pragma unroll
            for (int q = 0; q < 4; q++) {
                int co = wm * 32 + mf * 16 + g + ((q >> 1) << 3);
                int n = n0 + wn * 32 + gg * 8 + 2 * k3 + (q & 1);
                if (n < NSTA) {
                    float v = fmaxf(acc[mf][gg][q] + bias[co], 0.f);
                    out[(((long)(b * 128 + co)) * NSTA + n) * 17 + wo] = v;
                }
            }
        }
    }
#undef C3_ISSUE
}

// ---------------- GCN1 x@W on raw-reshape feature windows ----------------
__global__ void k_xw_feat(const float* __restrict__ x3, const float* __restrict__ wg,
                          float* __restrict__ h) {
    __shared__ float srow[4 * FEAT];
    int b = blockIdx.x / 142, ng = blockIdx.x % 142;
    int n0 = ng * 4;
    int tid = threadIdx.x;
    for (int i = tid; i < 4 * FEAT; i += 256) {
        int j = i / FEAT, k = i % FEAT;
        int n = n0 + j;
        srow[i] = (n < NSTA) ? x3[((long)(b * NSTA + n)) * FEAT + k] : 0.f;
    }
    __syncthreads();
    int j = tid >> 6, o = tid & 63;
    int n = n0 + j;
    if (n >= NSTA) return;
    const float* sr = srow + j * FEAT;
    float acc = 0.f;
    for (int k = 0; k < FEAT; k++) acc += sr[k] * wg[k * 64 + o];
    h[((long)(b * NSTA + n)) * 64 + o] = acc;
}

__global__ void k_xw64(const float* __restrict__ x, const float* __restrict__ w,
                       float* __restrict__ h) {
    __shared__ float srow[64];
    long bs = blockIdx.x;
    int tid = threadIdx.x;
    srow[tid] = x[bs * 64 + tid];
    __syncthreads();
    float acc = 0.f;
    for (int k = 0; k < 64; k++) acc += srow[k] * w[k * 64 + tid];
    h[bs * 64 + tid] = acc;
}

template <int ACT>  // 0 = relu, 1 = tanh
__global__ void k_agg(const float* __restrict__ h, const float* __restrict__ normT,
                      const float* __restrict__ bias, float* __restrict__ out) {
    __shared__ float sn[4 * NSTA];
    int b = blockIdx.x / 142, cg = blockIdx.x % 142;
    int c0 = cg * 4;
    int tid = threadIdx.x;  // 64
    for (int i = tid; i < 4 * NSTA; i += 64) {
        int cc = i / NSTA, rr = i % NSTA;
        int c = c0 + cc;
        sn[i] = (c < NSTA) ? normT[c * NSTA + rr] : 0.f;
    }
    __syncthreads();
    float bv = bias[tid];
    float acc[4] = {bv, bv, bv, bv};
    const float* hb = h + (long)b * NSTA * 64;
    for (int rr = 0; rr < NSTA; rr++) {
        float hv = hb[rr * 64 + tid];
#pragma unroll
        for (int q = 0; q < 4; q++) acc[q] += sn[q * NSTA + rr] * hv;
    }
#pragma unroll
    for (int q = 0; q < 4; q++) {
        int c = c0 + q;
        if (c < NSTA) {
            float v = ACT ? tanhf(acc[q]) : fmaxf(acc[q], 0.f);
            out[((long)b * NSTA + c) * 64 + tid] = v;
        }
    }
}

// ---------------- fc1 ----------------
__global__ void k_fc1_part(const float* __restrict__ x, const float* __restrict__ w,
                           float* __restrict__ part) {
    __shared__ float sx[16 * 512];
    int o = blockIdx.x * 128 + threadIdx.x;
    int k0 = blockIdx.y * 4520, k1 = k0 + 4520;
    float acc[16] = {};
    for (int kc = k0; kc < k1; kc += 512) {
        int len = min(512, k1 - kc);
        __syncthreads();
        for (int i = threadIdx.x; i < 16 * len; i += 128) {
            int bb = i / len, kk = i % len;
            sx[bb * 512 + kk] = x[bb * FLAT + kc + kk];
        }
        __syncthreads();
        for (int kk = 0; kk < len; kk++) {
            float wv = w[(long)(kc + kk) * 1280 + o];
#pragma unroll
            for (int bb = 0; bb < 16; bb++) acc[bb] += sx[bb * 512 + kk] * wv;
        }
    }
    for (int bb = 0; bb < 16; bb++) part[(blockIdx.y * 16 + bb) * 1280 + o] = acc[bb];
}

__global__ void k_fc1_fin(const float* __restrict__ part, const float* __restrict__ bias,
                          float* __restrict__ fc1) {
    int idx = blockIdx.x * blockDim.x + threadIdx.x;
    if (idx < 16 * 1280) {
        int b = idx / 1280, o = idx % 1280;
        float s = bias[o];
        for (int ks = 0; ks < 8; ks++) s += part[(ks * 16 + b) * 1280 + o];
        fc1[idx] = fmaxf(s, 0.f);
    }
}

// ---------------- extra / z / heads ----------------
__global__ void k_extra(const float* __restrict__ mv, const float* __restrict__ w,
                        const float* __restrict__ bias, float* __restrict__ out) {
    __shared__ float sx[NSTA];
    int b = blockIdx.x;
    for (int i = threadIdx.x; i < NSTA; i += blockDim.x) sx[i] = mv[b * NSTA + i];
    __syncthreads();
    int j = threadIdx.x;
    if (j < NSTA) {
        float acc = bias[j];
        for (int i = 0; i < NSTA; i++) acc += sx[i] * w[i * NSTA + j];
        out[b * NSTA + j] = fmaxf(acc, 0.f);
    }
}

__global__ void k_buildz(const float* __restrict__ fc1, const float* __restrict__ meta,
                         const float* __restrict__ extra, float* __restrict__ z) {
    int b = blockIdx.x;
    for (int i = threadIdx.x; i < ZDIM; i += blockDim.x) {
        float v;
        if (i < 1280)      v = fc1[b * 1280 + i];
        else if (i < 1285) v = meta[b * 5 + (i - 1280)];
        else               v = extra[b * NSTA + (i - 1285)];
        z[b * ZDIM + i] = v;
    }
}

__global__ void k_heads(const float* __restrict__ z,
                        const float* w0, const float* b0, const float* w1, const float* b1,
                        const float* w2, const float* b2, const float* w3, const float* b3,
                        const float* w4, const float* b4, float* __restrict__ out) {
    extern __shared__ float sz[];  // 16 * 1850
    const float* ws[5] = {w0, w1, w2, w3, w4};
    const float* bs[5] = {b0, b1, b2, b3, b4};
    int h = blockIdx.y;
    const float* w = ws[h];
    const float* bias = bs[h];
    int tid = threadIdx.x;
    for (int i = tid; i < 16 * ZDIM; i += 128) sz[i] = z[i];
    __syncthreads();
    int j = blockIdx.x * 128 + tid;
    if (j >= NSTA) return;
    float acc[16] = {};
    for (int k = 0; k < ZDIM; k++) {
        float wv = w[k * NSTA + j];
#pragma unroll
        for (int b = 0; b < 16; b++) acc[b] += sz[b * ZDIM + k] * wv;
    }
    float bb = bias[j];
    for (int b = 0; b < 16; b++) out[(h * 16 + b) * NSTA + j] = acc[b] + bb;
}

// ---------------- launch ----------------
extern "C" void kernel_launch(void* const* d_in, const int* in_sizes, int n_in,
                              void* d_out, int out_size) {
    const float* wav  = (const float*)d_in[0];
    const float* A    = (const float*)d_in[2];
    const float* meta = (const float*)d_in[3];
    const float* mv   = (const float*)d_in[4];
    const float* w1 = (const float*)d_in[5];  const float* b1 = (const float*)d_in[6];
    const float* w2 = (const float*)d_in[7];  const float* b2 = (const float*)d_in[8];
    const float* w3 = (const float*)d_in[9];  const float* b3 = (const float*)d_in[10];
    const float* wg1 = (const float*)d_in[11]; const float* bg1 = (const float*)d_in[12];
    const float* wg2 = (const float*)d_in[13]; const float* bg2 = (const float*)d_in[14];
    const float* wfe = (const float*)d_in[15]; const float* bfe = (const float*)d_in[16];
    const float* wf1 = (const float*)d_in[17]; const float* bf1 = (const float*)d_in[18];
    const float* wpga = (const float*)d_in[19]; const float* bpga = (const float*)d_in[20];
    const float* wpgv = (const float*)d_in[21]; const float* bpgv = (const float*)d_in[22];
    const float* ws03 = (const float*)d_in[23]; const float* bs03 = (const float*)d_in[24];
    const float* ws10 = (const float*)d_in[25]; const float* bs10 = (const float*)d_in[26];
    const float* ws30 = (const float*)d_in[27]; const float* bs30 = (const float*)d_in[28];
    float* out = (float*)d_out;

    uint32_t *pw1h, *pw1l, *pw2h, *pw2l, *pw3h, *pw3l;
    uint32_t *px1h, *px1l, *px2h, *px2l;
    float *px3, *pdinv, *pnorm, *pA, *pB, *ppart, *pfc1, *pextra, *pz;
    cudaGetSymbolAddress((void**)&pw1h, g_w1h);
    cudaGetSymbolAddress((void**)&pw1l, g_w1l);
    cudaGetSymbolAddress((void**)&pw2h, g_w2h);
    cudaGetSymbolAddress((void**)&pw2l, g_w2l);
    cudaGetSymbolAddress((void**)&pw3h, g_w3h);
    cudaGetSymbolAddress((void**)&pw3l, g_w3l);
    cudaGetSymbolAddress((void**)&px1h, g_x1h);
    cudaGetSymbolAddress((void**)&px1l, g_x1l);
    cudaGetSymbolAddress((void**)&px2h, g_x2h);
    cudaGetSymbolAddress((void**)&px2l, g_x2l);
    cudaGetSymbolAddress((void**)&px3, g_x3);
    cudaGetSymbolAddress((void**)&pdinv, g_dinv);
    cudaGetSymbolAddress((void**)&pnorm, g_normT);
    cudaGetSymbolAddress((void**)&pA, g_bufA);
    cudaGetSymbolAddress((void**)&pB, g_bufB);
    cudaGetSymbolAddress((void**)&ppart, g_fc1p);
    cudaGetSymbolAddress((void**)&pfc1, g_fc1);
    cudaGetSymbolAddress((void**)&pextra, g_extra);
    cudaGetSymbolAddress((void**)&pz, g_z);

    const int SM1 = (2 * 3 * 516 + 2 * 3 * 32 * 68) * 4;     // 64,608
    const int SM2 = (2 * 32 * 456 + 2 * 2 * 64 * 68) * 4;    // 186,368
    const int SM3 = (2 * 2 * 64 * 72 + 2 * 2 * 128 * 68) * 4; // 212,992
    const int SMH = 16 * ZDIM * 4;                           // 118,400
    cudaFuncSetAttribute(k_conv1n, cudaFuncAttributeMaxDynamicSharedMemorySize, SM1);
    cudaFuncSetAttribute(k_conv2n, cudaFuncAttributeMaxDynamicSharedMemorySize, SM2);
    cudaFuncSetAttribute(k_conv3n, cudaFuncAttributeMaxDynamicSharedMemorySize, SM3);
    cudaFuncSetAttribute(k_heads, cudaFuncAttributeMaxDynamicSharedMemorySize, SMH);

    k_wprep<<<(32 * 3 * 64 + 255) / 256, 256>>>(w1, pw1h, pw1l, 32 * 3 * 64);
    k_wprep<<<(64 * 32 * 64 + 255) / 256, 256>>>(w2, pw2h, pw2l, 64 * 32 * 64);
    k_wprep<<<(128 * 64 * 64 + 255) / 256, 256>>>(w3, pw3h, pw3l, 128 * 64 * 64);

    k_deg<<<NSTA, 64>>>(A, pdinv);
    k_norm<<<NSTA, 256>>>(A, pdinv, pnorm);

    k_conv1n<<<BATCH * NSTA, 256, SM1>>>(wav, pw1h, pw1l, b1, px1h, px1l);
    k_conv2n<<<BATCH * 283, 256, SM2>>>(px1h, px1l, pw2h, pw2l, b2, px2h, px2l);
    k_conv3n<<<BATCH * 17 * 9, 256, SM3>>>(px2h, px2l, pw3h, pw3l, b3, px3);

    k_xw_feat<<<BATCH * 142, 256>>>(px3, wg1, pA);
    k_agg<0><<<BATCH * 142, 64>>>(pA, pnorm, bg1, pB);
    k_xw64<<<BATCH * NSTA, 64>>>(pB, wg2, pA);
    k_agg<1><<<BATCH * 142, 64>>>(pA, pnorm, bg2, pB);

    k_fc1_part<<<dim3(10, 8), 128>>>(pB, wf1, ppart);
    k_fc1_fin<<<80, 256>>>(ppart, bf1, pfc1);
    k_extra<<<BATCH, 576>>>(mv, wfe, bfe, pextra);
    k_buildz<<<BATCH, 256>>>(pfc1, meta, pextra, pz);

    k_heads<<<dim3(5, 5), 128, SMH>>>(pz, wpga, bpga, wpgv, bpgv, ws03, bs03,
                                      ws10, bs10, ws30, bs30, out);
}

// round 17
// speedup vs baseline: 1.3870x; 1.3244x over previous
#include <cuda_runtime.h>
#include <cuda_fp16.h>
#include <math.h>
#include <stdint.h>

#define BATCH 16
#define NSTA  565
#define FEAT  2176
#define FLAT  36160
#define ZDIM  1850

// weights: fp16x2 hi/lo pairs; activations: single fp16x2 words
__device__ __align__(16) uint32_t g_w1h[32 * 3 * 64],   g_w1l[32 * 3 * 64];
__device__ __align__(16) uint32_t g_w2h[64 * 32 * 64],  g_w2l[64 * 32 * 64];
__device__ __align__(16) uint32_t g_w3h[128 * 64 * 64], g_w3l[128 * 64 * 64];
__device__ __align__(16) uint32_t g_x1h[(size_t)BATCH * 32 * NSTA * 224];  // [b][co][n][224w]
__device__ __align__(16) uint32_t g_x2h[(size_t)BATCH * 64 * 80 * 568];    // [b][co][m][568n]
__device__ float g_x3[(size_t)BATCH * 128 * NSTA * 17];
__device__ float g_dinv[NSTA];
__device__ float g_normT[NSTA * NSTA];
__device__ float g_bufA[BATCH * NSTA * 64];
__device__ float g_bufB[BATCH * NSTA * 64];
__device__ float g_fc1p[8 * BATCH * 1280];
__device__ float g_fc1[BATCH * 1280];
__device__ float g_extra[BATCH * NSTA];
__device__ float g_z[BATCH * ZDIM];

__device__ __forceinline__ uint32_t pack2h(float a, float b) {
    __half2 h = __floats2half2_rn(a, b);
    return *reinterpret_cast<uint32_t*>(&h);
}
// mma m16n8k16 f16 inputs, f32 accum
__device__ __forceinline__ void mmah(float* c, const uint32_t* a, uint32_t b0, uint32_t b1) {
    asm volatile("mma.sync.aligned.m16n8k16.row.col.f32.f16.f16.f32 "
        "{%0,%1,%2,%3},{%4,%5,%6,%7},{%8,%9},{%0,%1,%2,%3};"
        : "+f"(c[0]), "+f"(c[1]), "+f"(c[2]), "+f"(c[3])
        : "r"(a[0]), "r"(a[1]), "r"(a[2]), "r"(a[3]), "r"(b0), "r"(b1));
}
__device__ __forceinline__ void cpa16(uint32_t d, const void* s) {
    asm volatile("cp.async.cg.shared.global [%0], [%1], 16;" :: "r"(d), "l"(s) : "memory");
}
#define CPA_COMMIT() asm volatile("cp.async.commit_group;" ::: "memory")
#define CPA_WAIT1()  asm volatile("cp.async.wait_group 1;" ::: "memory")

// weight prep: fp32 [CO][CI][125] -> fp16x2 hi/lo [CO][CI][64]
__global__ void k_wprep(const float* __restrict__ w, uint32_t* __restrict__ wh,
                        uint32_t* __restrict__ wl, int total) {
    int i = blockIdx.x * 256 + threadIdx.x;
    if (i >= total) return;
    int m = i & 63;
    const float* wr = w + (long)(i >> 6) * 125;
    float v0 = (2 * m < 125) ? wr[2 * m] : 0.f;
    float v1 = (2 * m + 1 < 125) ? wr[2 * m + 1] : 0.f;
    __half h0 = __float2half_rn(v0), h1 = __float2half_rn(v1);
    float l0 = v0 - __half2float(h0), l1 = v1 - __half2float(h1);
    wh[i] = pack2h(__half2float(h0), __half2float(h1));
    wl[i] = pack2h(l0, l1);
}

__global__ void k_deg(const float* __restrict__ A, float* __restrict__ dinv) {
    int c = blockIdx.x;
    float s = 0.f;
    for (int r = threadIdx.x; r < NSTA; r += 64) s += A[r * NSTA + c];
    __shared__ float red[64];
    red[threadIdx.x] = s; __syncthreads();
    for (int o = 32; o > 0; o >>= 1) {
        if (threadIdx.x < o) red[threadIdx.x] += red[threadIdx.x + o];
        __syncthreads();
    }
    if (threadIdx.x == 0) dinv[c] = rsqrtf(red[0] + 1.0f);
}
__global__ void k_norm(const float* __restrict__ A, const float* __restrict__ dinv,
                       float* __restrict__ normT) {
    int c = blockIdx.x;
    float dc = dinv[c];
    for (int r = threadIdx.x; r < NSTA; r += 256)
        normT[c * NSTA + r] = dinv[r] * (A[r * NSTA + c] + (r == c ? 1.0f : 0.0f)) * dc;
}

// ---------------- conv1: weights resident, B single fp16, 2 mma/k-step ----------------
__global__ void __launch_bounds__(256, 2)
k_conv1n(const float* __restrict__ wav, const uint32_t* __restrict__ wgh,
         const uint32_t* __restrict__ wgl, const float* __restrict__ bias,
         uint32_t* __restrict__ oh) {
    extern __shared__ uint32_t smu[];
    uint32_t* s_i  = smu;                 // 3*516 (fp16x2 t-pairs)
    uint32_t* s_wh = smu + 3 * 516;       // 3*2176
    uint32_t* s_wl = s_wh + 3 * 2176;
    const int b = blockIdx.x / NSTA, n = blockIdx.x % NSTA;
    const int tid = threadIdx.x, lane = tid & 31, wid = tid >> 5;
    const int wm = wid >> 2, wn = wid & 3;
    const int nbase = wn * 112;           // NG=14
    const int g = lane >> 2, k3 = lane & 3;
    for (int i = tid; i < 3 * 512; i += 256) {
        int ci = i / 512, m = i % 512;
        int t0 = 2 * m, t1 = t0 + 1;
        const float* base = wav + ((long)(b * NSTA + n)) * 3000 + ci;
        float v0 = (t0 < 1000) ? base[t0 * 3] : 0.f;
        float v1 = (t1 < 1000) ? base[t1 * 3] : 0.f;
        s_i[ci * 516 + m] = pack2h(v0, v1);
    }
    const uint4* wh4 = (const uint4*)wgh;
    const uint4* wl4 = (const uint4*)wgl;
    for (int i = tid; i < 1536; i += 256) {
        int co = i / 48, rr = i % 48, ci = rr >> 4, v = rr & 15;
        long src = ((long)co * 3 + ci) * 16 + v;
        *reinterpret_cast<uint4*>(s_wh + ci * 2176 + co * 68 + 4 * v) = wh4[src];
        *reinterpret_cast<uint4*>(s_wl + ci * 2176 + co * 68 + 4 * v) = wl4[src];
    }
    __syncthreads();
    float acc[14][4];
#pragma unroll
    for (int gg = 0; gg < 14; gg++)
#pragma unroll
        for (int q = 0; q < 4; q++) acc[gg][q] = 0.f;
    for (int ci = 0; ci < 3; ci++) {
        const uint32_t* swh = s_wh + ci * 2176;
        const uint32_t* swl = s_wl + ci * 2176;
        const uint32_t* bi = s_i + ci * 516;
#pragma unroll
        for (int ks = 0; ks < 8; ks++) {
            uint32_t Ah[4], Al[4];
            int co = wm * 16 + g;
            const uint32_t* p = swh + co * 68 + ks * 8 + k3;
            Ah[0] = p[0]; Ah[1] = p[8 * 68]; Ah[2] = p[4]; Ah[3] = p[8 * 68 + 4];
            const uint32_t* q = swl + co * 68 + ks * 8 + k3;
            Al[0] = q[0]; Al[1] = q[8 * 68]; Al[2] = q[4]; Al[3] = q[8 * 68 + 4];
#pragma unroll
            for (int gg = 0; gg < 14; gg++) {
                int widx = nbase + gg * 8 + g + ks * 8 + k3;
                uint32_t b0 = bi[widx], b1 = bi[widx + 4];
                mmah(acc[gg], Ah, b0, b1);
                mmah(acc[gg], Al, b0, b1);
            }
        }
    }
#pragma unroll
    for (int gg = 0; gg < 14; gg++) {
        int wo = nbase + gg * 8 + 2 * k3, m = wo >> 1;
#pragma unroll
        for (int half = 0; half < 2; half++) {
            int co = wm * 16 + g + half * 8;
            float bb = bias[co];
            float v0 = acc[gg][half * 2 + 0] + bb, v1 = acc[gg][half * 2 + 1] + bb;
            v0 = (wo < 438) ? fmaxf(v0, 0.f) : 0.f;
            v1 = (wo + 1 < 438) ? fmaxf(v1, 0.f) : 0.f;
            oh[(((long)(b * 32 + co)) * NSTA + n) * 224 + m] = pack2h(v0, v1);
        }
    }
}

// ---------------- conv2: 1 station x 32 co per CTA (128 thr), occ 3 ----------------
__global__ void __launch_bounds__(128, 3)
k_conv2n(const uint32_t* __restrict__ inh, const uint32_t* __restrict__ wgh,
         const uint32_t* __restrict__ wgl, const float* __restrict__ bias,
         uint32_t* __restrict__ oh) {
    extern __shared__ uint32_t smu[];
    uint32_t* s_i = smu;            // 32ci x 228
    uint32_t* s_w = smu + 32 * 228; // 2buf x (2hl x 32co x 68) = 8704 words
    const int bx = blockIdx.x;
    const int b = bx / 1130, rr = bx % 1130;
    const int n = rr >> 1, h = rr & 1;
    const int tid = threadIdx.x, lane = tid & 31, wn = tid >> 5;  // 4 warps = wn
    const int nbase = wn * 40;   // NG=5
    const int g = lane >> 2, k3 = lane & 3;
    const uint32_t swb = (uint32_t)__cvta_generic_to_shared(s_w);
    const uint4* wh4 = (const uint4*)wgh;
    const uint4* wl4 = (const uint4*)wgl;
    {
        const uint4* ih4 = (const uint4*)inh;
        for (int i = tid; i < 32 * 56; i += 128) {
            int ci = i / 56, v = i % 56;
            *reinterpret_cast<uint4*>(s_i + ci * 228 + 4 * v) =
                ih4[(((long)(b * 32 + ci)) * NSTA + n) * 56 + v];
        }
    }
#define C2_ISSUE(CI, BUF) do { \
        _Pragma("unroll") \
        for (int t = 0; t < 8; t++) { \
            int j = tid + t * 128; \
            int hl = j >> 9, co = (j >> 4) & 31, v = j & 15; \
            const uint4* src = (hl ? wl4 : wh4) + (((long)(h * 32 + co)) * 32 + (CI)) * 16 + v; \
            cpa16(swb + ((BUF) * 4352 + hl * 2176 + co * 68 + 4 * v) * 4, src); \
        } \
    } while (0)
    float acc[2][5][4];
#pragma unroll
    for (int mf = 0; mf < 2; mf++)
#pragma unroll
        for (int gg = 0; gg < 5; gg++)
#pragma unroll
            for (int q = 0; q < 4; q++) acc[mf][gg][q] = 0.f;
    C2_ISSUE(0, 0);
    CPA_COMMIT();
    for (int ci = 0; ci < 32; ci++) {
        if (ci + 1 < 32) C2_ISSUE(ci + 1, (ci + 1) & 1);
        CPA_COMMIT();
        CPA_WAIT1();
        __syncthreads();
        const uint32_t* swh = s_w + (ci & 1) * 4352;
        const uint32_t* swl = swh + 2176;
        const uint32_t* bi = s_i + ci * 228;
#pragma unroll
        for (int ks = 0; ks < 8; ks++) {
            uint32_t Ah[2][4], Al[2][4];
#pragma unroll
            for (int mf = 0; mf < 2; mf++) {
                int col = mf * 16 + g;
                const uint32_t* p = swh + col * 68 + ks * 8 + k3;
                Ah[mf][0] = p[0]; Ah[mf][1] = p[8 * 68]; Ah[mf][2] = p[4]; Ah[mf][3] = p[8 * 68 + 4];
                const uint32_t* q = swl + col * 68 + ks * 8 + k3;
                Al[mf][0] = q[0]; Al[mf][1] = q[8 * 68]; Al[mf][2] = q[4]; Al[mf][3] = q[8 * 68 + 4];
            }
#pragma unroll
            for (int gg = 0; gg < 5; gg++) {
                int widx = nbase + gg * 8 + g + ks * 8 + k3;
                uint32_t b0 = bi[widx], b1 = bi[widx + 4];
#pragma unroll
                for (int mf = 0; mf < 2; mf++) {
                    mmah(acc[mf][gg], Ah[mf], b0, b1);
                    mmah(acc[mf][gg], Al[mf], b0, b1);
                }
            }
        }
        __syncthreads();
    }
#pragma unroll
    for (int mf = 0; mf < 2; mf++) {
#pragma unroll
        for (int gg = 0; gg < 5; gg++) {
            int wo = nbase + gg * 8 + 2 * k3, m = wo >> 1;
#pragma unroll
            for (int half = 0; half < 2; half++) {
                int co = h * 32 + mf * 16 + g + half * 8;
                float bb = bias[co];
                float v0 = acc[mf][gg][half * 2 + 0] + bb, v1 = acc[mf][gg][half * 2 + 1] + bb;
                v0 = (wo < 157) ? fmaxf(v0, 0.f) : 0.f;
                v1 = (wo + 1 < 157) ? fmaxf(v1, 0.f) : 0.f;
                oh[(((long)(b * 64 + co)) * 80 + m) * 568 + n] = pack2h(v0, v1);
            }
        }
    }
#undef C2_ISSUE
}

// ---------------- conv3: cp.async double-buffered, B single fp16 ----------------
__global__ void __launch_bounds__(256, 1)
k_conv3n(const uint32_t* __restrict__ x2h, const uint32_t* __restrict__ wgh,
         const uint32_t* __restrict__ wgl, const float* __restrict__ bias,
         float* __restrict__ out) {
    extern __shared__ uint32_t smu[];
    uint32_t* s_p = smu;            // 2buf x 64 x 72
    uint32_t* s_w = smu + 9216;     // 2buf x (2hl x 128 x 68)
    const int cta = blockIdx.x;
    const int b = cta / 153, r = cta % 153;
    const int wo = r / 9, nt = r % 9;
    const int n0 = (nt == 8) ? 504 : nt * 64;
    const int tid = threadIdx.x, lane = tid & 31, wid = tid >> 5;
    const int wm = wid >> 1, wn = wid & 1;
    const int g = lane >> 2, k3 = lane & 3;
    const uint32_t spb = (uint32_t)__cvta_generic_to_shared(s_p);
    const uint32_t swb = (uint32_t)__cvta_generic_to_shared(s_w);
    const uint4* wh4 = (const uint4*)wgh;
    const uint4* wl4 = (const uint4*)wgl;
    const uint4* ph4 = (const uint4*)x2h;
    const int nw4 = n0 >> 2;
#define C3_ISSUE(CI, BUF) do { \
        _Pragma("unroll") \
        for (int t = 0; t < 16; t++) { \
            int j = tid + t * 256; \
            int hl = j >> 11, co = (j >> 4) & 127, v = j & 15; \
            const uint4* src = (hl ? wl4 : wh4) + ((long)co * 64 + (CI)) * 16 + v; \
            cpa16(swb + ((BUF) * 17408 + hl * 8704 + co * 68 + 4 * v) * 4, src); \
        } \
        _Pragma("unroll") \
        for (int t = 0; t < 4; t++) { \
            int j = tid + t * 256; \
            int m = j >> 4, v = j & 15; \
            long row = ((long)(b * 64 + (CI))) * 80 + wo + m; \
            cpa16(spb + ((BUF) * 4608 + m * 72 + 4 * v) * 4, ph4 + row * 142 + nw4 + v); \
        } \
    } while (0)
    float acc[2][4][4];
#pragma unroll
    for (int mf = 0; mf < 2; mf++)
#pragma unroll
        for (int gg = 0; gg < 4; gg++)
#pragma unroll
            for (int q = 0; q < 4; q++) acc[mf][gg][q] = 0.f;
    C3_ISSUE(0, 0);
    CPA_COMMIT();
    for (int ci = 0; ci < 64; ci++) {
        if (ci + 1 < 64) C3_ISSUE(ci + 1, (ci + 1) & 1);
        CPA_COMMIT();
        CPA_WAIT1();
        __syncthreads();
        const uint32_t* swh = s_w + (ci & 1) * 17408;
        const uint32_t* swl = swh + 8704;
        const uint32_t* sph = s_p + (ci & 1) * 4608;
#pragma unroll
        for (int ks = 0; ks < 8; ks++) {
            uint32_t Ah[2][4], Al[2][4];
#pragma unroll
            for (int mf = 0; mf < 2; mf++) {
                int co = wm * 32 + mf * 16 + g;
                const uint32_t* p = swh + co * 68 + ks * 8 + k3;
                Ah[mf][0] = p[0]; Ah[mf][1] = p[8 * 68]; Ah[mf][2] = p[4]; Ah[mf][3] = p[8 * 68 + 4];
                const uint32_t* q = swl + co * 68 + ks * 8 + k3;
                Al[mf][0] = q[0]; Al[mf][1] = q[8 * 68]; Al[mf][2] = q[4]; Al[mf][3] = q[8 * 68 + 4];
            }
#pragma unroll
            for (int gg = 0; gg < 4; gg++) {
                int base = (ks * 8 + k3) * 72 + wn * 32 + gg * 8 + g;
                uint32_t b0 = sph[base], b1 = sph[base + 4 * 72];
#pragma unroll
                for (int mf = 0; mf < 2; mf++) {
                    mmah(acc[mf][gg], Ah[mf], b0, b1);
                    mmah(acc[mf][gg], Al[mf], b0, b1);
                }
            }
        }
        __syncthreads();
    }
#pragma unroll
    for (int mf = 0; mf < 2; mf++) {
#pragma unroll
        for (int gg = 0; gg < 4; gg++) {
#pragma unroll
            for (int q = 0; q < 4; q++) {
                int co = wm * 32 + mf * 16 + g + ((q >> 1) << 3);
                int n = n0 + wn * 32 + gg * 8 + 2 * k3 + (q & 1);
                if (n < NSTA) {
                    float v = fmaxf(acc[mf][gg][q] + bias[co], 0.f);
                    out[(((long)(b * 128 + co)) * NSTA + n) * 17 + wo] = v;
                }
            }
        }
    }
#undef C3_ISSUE
}

__global__ void k_xw_feat(const float* __restrict__ x3, const float* __restrict__ wg,
                          float* __restrict__ h) {
    __shared__ float srow[4 * FEAT];
    int b = blockIdx.x / 142, ng = blockIdx.x % 142;
    int n0 = ng * 4;
    int tid = threadIdx.x;
    for (int i = tid; i < 4 * FEAT; i += 256) {
        int j = i / FEAT, k = i % FEAT;
        int n = n0 + j;
        srow[i] = (n < NSTA) ? x3[((long)(b * NSTA + n)) * FEAT + k] : 0.f;
    }
    __syncthreads();
    int j = tid >> 6, o = tid & 63;
    int n = n0 + j;
    if (n >= NSTA) return;
    const float* sr = srow + j * FEAT;
    float acc = 0.f;
    for (int k = 0; k < FEAT; k++) acc += sr[k] * wg[k * 64 + o];
    h[((long)(b * NSTA + n)) * 64 + o] = acc;
}
__global__ void k_xw64(const float* __restrict__ x, const float* __restrict__ w,
                       float* __restrict__ h) {
    __shared__ float srow[64];
    long bs = blockIdx.x;
    int tid = threadIdx.x;
    srow[tid] = x[bs * 64 + tid];
    __syncthreads();
    float acc = 0.f;
    for (int k = 0; k < 64; k++) acc += srow[k] * w[k * 64 + tid];
    h[bs * 64 + tid] = acc;
}
template <int ACT>
__global__ void k_agg(const float* __restrict__ h, const float* __restrict__ normT,
                      const float* __restrict__ bias, float* __restrict__ out) {
    __shared__ float sn[4 * NSTA];
    int b = blockIdx.x / 142, cg = blockIdx.x % 142;
    int c0 = cg * 4;
    int tid = threadIdx.x;
    for (int i = tid; i < 4 * NSTA; i += 64) {
        int cc = i / NSTA, rr = i % NSTA, c = c0 + cc;
        sn[i] = (c < NSTA) ? normT[c * NSTA + rr] : 0.f;
    }
    __syncthreads();
    float bv = bias[tid];
    float acc[4] = {bv, bv, bv, bv};
    const float* hb = h + (long)b * NSTA * 64;
    for (int rr = 0; rr < NSTA; rr++) {
        float hv = hb[rr * 64 + tid];
#pragma unroll
        for (int q = 0; q < 4; q++) acc[q] += sn[q * NSTA + rr] * hv;
    }
#pragma unroll
    for (int q = 0; q < 4; q++) {
        int c = c0 + q;
        if (c < NSTA) {
            float v = ACT ? tanhf(acc[q]) : fmaxf(acc[q], 0.f);
            out[((long)b * NSTA + c) * 64 + tid] = v;
        }
    }
}
__global__ void k_fc1_part(const float* __restrict__ x, const float* __restrict__ w,
                           float* __restrict__ part) {
    __shared__ float sx[16 * 512];
    int o = blockIdx.x * 128 + threadIdx.x;
    int k0 = blockIdx.y * 4520, k1 = k0 + 4520;
    float acc[16] = {};
    for (int kc = k0; kc < k1; kc += 512) {
        int len = min(512, k1 - kc);
        __syncthreads();
        for (int i = threadIdx.x; i < 16 * len; i += 128) {
            int bb = i / len, kk = i % len;
            sx[bb * 512 + kk] = x[bb * FLAT + kc + kk];
        }
        __syncthreads();
        for (int kk = 0; kk < len; kk++) {
            float wv = w[(long)(kc + kk) * 1280 + o];
#pragma unroll
            for (int bb = 0; bb < 16; bb++) acc[bb] += sx[bb * 512 + kk] * wv;
        }
    }
    for (int bb = 0; bb < 16; bb++) part[(blockIdx.y * 16 + bb) * 1280 + o] = acc[bb];
}
__global__ void k_fc1_fin(const float* __restrict__ part, const float* __restrict__ bias,
                          float* __restrict__ fc1) {
    int idx = blockIdx.x * blockDim.x + threadIdx.x;
    if (idx < 16 * 1280) {
        int b = idx / 1280, o = idx % 1280;
        float s = bias[o];
        for (int ks = 0; ks < 8; ks++) s += part[(ks * 16 + b) * 1280 + o];
        fc1[idx] = fmaxf(s, 0.f);
    }
}
__global__ void k_extra(const float* __restrict__ mv, const float* __restrict__ w,
                        const float* __restrict__ bias, float* __restrict__ out) {
    __shared__ float sx[NSTA];
    int b = blockIdx.x;
    for (int i = threadIdx.x; i < NSTA; i += blockDim.x) sx[i] = mv[b * NSTA + i];
    __syncthreads();
    int j = threadIdx.x;
    if (j < NSTA) {
        float acc = bias[j];
        for (int i = 0; i < NSTA; i++) acc += sx[i] * w[i * NSTA + j];
        out[b * NSTA + j] = fmaxf(acc, 0.f);
    }
}
__global__ void k_buildz(const float* __restrict__ fc1, const float* __restrict__ meta,
                         const float* __restrict__ extra, float* __restrict__ z) {
    int b = blockIdx.x;
    for (int i = threadIdx.x; i < ZDIM; i += blockDim.x) {
        float v;
        if (i < 1280)      v = fc1[b * 1280 + i];
        else if (i < 1285) v = meta[b * 5 + (i - 1280)];
        else               v = extra[b * NSTA + (i - 1285)];
        z[b * ZDIM + i] = v;
    }
}
__global__ void k_heads(const float* __restrict__ z,
                        const float* w0, const float* b0, const float* w1, const float* b1,
                        const float* w2, const float* b2, const float* w3, const float* b3,
                        const float* w4, const float* b4, float* __restrict__ out) {
    extern __shared__ float sz[];
    const float* ws[5] = {w0, w1, w2, w3, w4};
    const float* bs[5] = {b0, b1, b2, b3, b4};
    int h = blockIdx.y;
    const float* w = ws[h];
    const float* bias = bs[h];
    int tid = threadIdx.x;
    for (int i = tid; i < 16 * ZDIM; i += 128) sz[i] = z[i];
    __syncthreads();
    int j = blockIdx.x * 128 + tid;
    if (j >= NSTA) return;
    float acc[16] = {};
    for (int k = 0; k < ZDIM; k++) {
        float wv = w[k * NSTA + j];
#pragma unroll
        for (int b = 0; b < 16; b++) acc[b] += sz[b * ZDIM + k] * wv;
    }
    float bb = bias[j];
    for (int b = 0; b < 16; b++) out[(h * 16 + b) * NSTA + j] = acc[b] + bb;
}

extern "C" void kernel_launch(void* const* d_in, const int* in_sizes, int n_in,
                              void* d_out, int out_size) {
    const float* wav  = (const float*)d_in[0];
    const float* A    = (const float*)d_in[2];
    const float* meta = (const float*)d_in[3];
    const float* mv   = (const float*)d_in[4];
    const float* w1 = (const float*)d_in[5];  const float* b1 = (const float*)d_in[6];
    const float* w2 = (const float*)d_in[7];  const float* b2 = (const float*)d_in[8];
    const float* w3 = (const float*)d_in[9];  const float* b3 = (const float*)d_in[10];
    const float* wg1 = (const float*)d_in[11]; const float* bg1 = (const float*)d_in[12];
    const float* wg2 = (const float*)d_in[13]; const float* bg2 = (const float*)d_in[14];
    const float* wfe = (const float*)d_in[15]; const float* bfe = (const float*)d_in[16];
    const float* wf1 = (const float*)d_in[17]; const float* bf1 = (const float*)d_in[18];
    const float* wpga = (const float*)d_in[19]; const float* bpga = (const float*)d_in[20];
    const float* wpgv = (const float*)d_in[21]; const float* bpgv = (const float*)d_in[22];
    const float* ws03 = (const float*)d_in[23]; const float* bs03 = (const float*)d_in[24];
    const float* ws10 = (const float*)d_in[25]; const float* bs10 = (const float*)d_in[26];
    const float* ws30 = (const float*)d_in[27]; const float* bs30 = (const float*)d_in[28];
    float* out = (float*)d_out;

    uint32_t *pw1h, *pw1l, *pw2h, *pw2l, *pw3h, *pw3l, *px1h, *px2h;
    float *px3, *pdinv, *pnorm, *pA, *pB, *ppart, *pfc1, *pextra, *pz;
    cudaGetSymbolAddress((void**)&pw1h, g_w1h);
    cudaGetSymbolAddress((void**)&pw1l, g_w1l);
    cudaGetSymbolAddress((void**)&pw2h, g_w2h);
    cudaGetSymbolAddress((void**)&pw2l, g_w2l);
    cudaGetSymbolAddress((void**)&pw3h, g_w3h);
    cudaGetSymbolAddress((void**)&pw3l, g_w3l);
    cudaGetSymbolAddress((void**)&px1h, g_x1h);
    cudaGetSymbolAddress((void**)&px2h, g_x2h);
    cudaGetSymbolAddress((void**)&px3, g_x3);
    cudaGetSymbolAddress((void**)&pdinv, g_dinv);
    cudaGetSymbolAddress((void**)&pnorm, g_normT);
    cudaGetSymbolAddress((void**)&pA, g_bufA);
    cudaGetSymbolAddress((void**)&pB, g_bufB);
    cudaGetSymbolAddress((void**)&ppart, g_fc1p);
    cudaGetSymbolAddress((void**)&pfc1, g_fc1);
    cudaGetSymbolAddress((void**)&pextra, g_extra);
    cudaGetSymbolAddress((void**)&pz, g_z);

    const int SM1 = (3 * 516 + 2 * 3 * 2176) * 4;          // 58,416
    const int SM2 = (32 * 228 + 2 * 2 * 32 * 68) * 4;      // 64,000
    const int SM3 = (2 * 64 * 72 + 2 * 2 * 128 * 68) * 4;  // 176,128
    const int SMH = 16 * ZDIM * 4;
    cudaFuncSetAttribute(k_conv1n, cudaFuncAttributeMaxDynamicSharedMemorySize, SM1);
    cudaFuncSetAttribute(k_conv2n, cudaFuncAttributeMaxDynamicSharedMemorySize, SM2);
    cudaFuncSetAttribute(k_conv3n, cudaFuncAttributeMaxDynamicSharedMemorySize, SM3);
    cudaFuncSetAttribute(k_heads, cudaFuncAttributeMaxDynamicSharedMemorySize, SMH);

    k_wprep<<<(32 * 3 * 64 + 255) / 256, 256>>>(w1, pw1h, pw1l, 32 * 3 * 64);
    k_wprep<<<(64 * 32 * 64 + 255) / 256, 256>>>(w2, pw2h, pw2l, 64 * 32 * 64);
    k_wprep<<<(128 * 64 * 64 + 255) / 256, 256>>>(w3, pw3h, pw3l, 128 * 64 * 64);
    k_deg<<<NSTA, 64>>>(A, pdinv);
    k_norm<<<NSTA, 256>>>(A, pdinv, pnorm);

    k_conv1n<<<BATCH * NSTA, 256, SM1>>>(wav, pw1h, pw1l, b1, px1h);
    k_conv2n<<<BATCH * NSTA * 2, 128, SM2>>>(px1h, pw2h, pw2l, b2, px2h);
    k_conv3n<<<BATCH * 17 * 9, 256, SM3>>>(px2h, pw3h, pw3l, b3, px3);

    k_xw_feat<<<BATCH * 142, 256>>>(px3, wg1, pA);
    k_agg<0><<<BATCH * 142, 64>>>(pA, pnorm, bg1, pB);
    k_xw64<<<BATCH * NSTA, 64>>>(pB, wg2, pA);
    k_agg<1><<<BATCH * 142, 64>>>(pA, pnorm, bg2, pB);
    k_fc1_part<<<dim3(10, 8), 128>>>(pB, wf1, ppart);
    k_fc1_fin<<<80, 256>>>(ppart, bf1, pfc1);
    k_extra<<<BATCH, 576>>>(mv, wfe, bfe, pextra);
    k_buildz<<<BATCH, 256>>>(pfc1, meta, pextra, pz);
    k_heads<<<dim3(5, 5), 128, SMH>>>(pz, wpga, bpga, wpgv, bpgv, ws03, bs03,
                                      ws10, bs10, ws30, bs30, out);
}